// round 1
// baseline (speedup 1.0000x reference)
#include <cuda_runtime.h>
#include <math.h>

#define SRC 50
#define TRGN 50
#define BSZ 32
#define EMBED 620
#define ECH 1000
#define DCH 1000
#define VOCAB 30000
#define NSTEP 49
#define MROWS (NSTEP*BSZ)          /* 1568 */
#define C2W (EMBED + DCH + 2*ECH)  /* 3620 */

// ---------------- scratch (static device memory; no allocations) ----------------
__device__ float d_annProj[SRC*BSZ*DCH];    // annotations @ W_c[:,1000:].T + b_c
__device__ float d_hbuf[2][BSZ*DCH];        // ping-pong hidden
__device__ float d_hProj[BSZ*DCH];          // h @ W_c[:,:1000].T
__device__ float d_gi[BSZ*3*DCH];
__device__ float d_gh[BSZ*3*DCH];
__device__ float d_attnS[SRC*BSZ];
__device__ float d_comb2[(size_t)MROWS*C2W]; // [emb | h_prev | ctx] per (step,b)
__device__ float d_giEmb[(size_t)MROWS*3*DCH];

// ---------------- generic fp32 GEMM: C = act(A @ B^T + bias + Dadd) -------------
// A: [M,K] lda, B: [N,K] ldb, C: [M,N] ldc. 128x128x8 tile, 8x8 micro.
__global__ __launch_bounds__(256) void k_sgemm(
    const float* __restrict__ A, int lda,
    const float* __restrict__ Bm, int ldb,
    const float* __restrict__ bias,
    const float* __restrict__ Dadd, int ldd,
    float* __restrict__ C, int ldc,
    int M, int N, int K, int act)
{
    __shared__ float As[8][128];
    __shared__ float Bs[8][128];

    const int tid = threadIdx.x;
    const int m0 = blockIdx.y * 128;
    const int n0 = blockIdx.x * 128;

    const int w = tid >> 5, lane = tid & 31;
    const int trow = ((w >> 1) << 5) + ((lane >> 3) << 3); // 0..127
    const int tcol = ((w & 1) << 6) + ((lane & 7) << 3);   // 0..127

    const int lrow = tid >> 1;        // 0..127
    const int lk   = (tid & 1) << 2;  // 0 or 4

    float acc[8][8];
#pragma unroll
    for (int i = 0; i < 8; i++)
#pragma unroll
        for (int j = 0; j < 8; j++) acc[i][j] = 0.f;

    for (int k0 = 0; k0 < K; k0 += 8) {
        // load A tile (transposed into smem)
        {
            float4 v = make_float4(0.f, 0.f, 0.f, 0.f);
            int gm = m0 + lrow;
            int gk = k0 + lk;
            if (gm < M) {
                if (gk + 3 < K) {
                    v = *reinterpret_cast<const float4*>(A + (size_t)gm * lda + gk);
                } else {
                    float t0 = (gk + 0 < K) ? A[(size_t)gm * lda + gk + 0] : 0.f;
                    float t1 = (gk + 1 < K) ? A[(size_t)gm * lda + gk + 1] : 0.f;
                    float t2 = (gk + 2 < K) ? A[(size_t)gm * lda + gk + 2] : 0.f;
                    float t3 = (gk + 3 < K) ? A[(size_t)gm * lda + gk + 3] : 0.f;
                    v = make_float4(t0, t1, t2, t3);
                }
            }
            As[lk + 0][lrow] = v.x; As[lk + 1][lrow] = v.y;
            As[lk + 2][lrow] = v.z; As[lk + 3][lrow] = v.w;
        }
        // load B tile
        {
            float4 v = make_float4(0.f, 0.f, 0.f, 0.f);
            int gn = n0 + lrow;
            int gk = k0 + lk;
            if (gn < N) {
                if (gk + 3 < K) {
                    v = *reinterpret_cast<const float4*>(Bm + (size_t)gn * ldb + gk);
                } else {
                    float t0 = (gk + 0 < K) ? Bm[(size_t)gn * ldb + gk + 0] : 0.f;
                    float t1 = (gk + 1 < K) ? Bm[(size_t)gn * ldb + gk + 1] : 0.f;
                    float t2 = (gk + 2 < K) ? Bm[(size_t)gn * ldb + gk + 2] : 0.f;
                    float t3 = (gk + 3 < K) ? Bm[(size_t)gn * ldb + gk + 3] : 0.f;
                    v = make_float4(t0, t1, t2, t3);
                }
            }
            Bs[lk + 0][lrow] = v.x; Bs[lk + 1][lrow] = v.y;
            Bs[lk + 2][lrow] = v.z; Bs[lk + 3][lrow] = v.w;
        }
        __syncthreads();
#pragma unroll
        for (int kk = 0; kk < 8; kk++) {
            float a[8], b[8];
            *reinterpret_cast<float4*>(a)     = *reinterpret_cast<const float4*>(&As[kk][trow]);
            *reinterpret_cast<float4*>(a + 4) = *reinterpret_cast<const float4*>(&As[kk][trow + 4]);
            *reinterpret_cast<float4*>(b)     = *reinterpret_cast<const float4*>(&Bs[kk][tcol]);
            *reinterpret_cast<float4*>(b + 4) = *reinterpret_cast<const float4*>(&Bs[kk][tcol + 4]);
#pragma unroll
            for (int i = 0; i < 8; i++)
#pragma unroll
                for (int j = 0; j < 8; j++)
                    acc[i][j] = fmaf(a[i], b[j], acc[i][j]);
        }
        __syncthreads();
    }

#pragma unroll
    for (int i = 0; i < 8; i++) {
        int gm = m0 + trow + i;
        if (gm >= M) continue;
#pragma unroll
        for (int j = 0; j < 8; j++) {
            int gn = n0 + tcol + j;
            if (gn >= N) continue;
            float v = acc[i][j];
            if (bias) v += bias[gn];
            if (Dadd) v += Dadd[(size_t)gm * ldd + gn];
            if (act) v = tanhf(v);
            C[(size_t)gm * ldc + gn] = v;
        }
    }
}

// ------------- zero preds[0] and attns[0] -------------
__global__ void k_zero(float* __restrict__ preds0, float* __restrict__ attns0, int n)
{
    int i = blockIdx.x * blockDim.x + threadIdx.x;
    if (i < n) preds0[i] = 0.f;
    if (i < SRC * BSZ) attns0[i] = 0.f;
}

// ------------- gather embeddings into combined2[:, 0:620] -------------
__global__ void k_embed(const int* __restrict__ tok, const float* __restrict__ emb)
{
    int i = blockIdx.x * blockDim.x + threadIdx.x;
    if (i >= MROWS * EMBED) return;
    int m = i / EMBED, e = i - m * EMBED;
    d_comb2[(size_t)m * C2W + e] = emb[(size_t)tok[m] * EMBED + e];
}

// ------------- attention scores + softmax over BATCH axis -------------
// grid: 50 blocks (one per source position s), 256 threads
__global__ void k_attn(const float* __restrict__ w_a, float* __restrict__ attn_out)
{
    int s = blockIdx.x;
    int t = threadIdx.x;
    int b = t >> 3, jt = t & 7;
    const float* hp = d_hProj + b * DCH;
    const float* ap = d_annProj + (size_t)(s * BSZ + b) * DCH;
    float acc = 0.f;
    for (int j = jt; j < DCH; j += 8)
        acc += tanhf(hp[j] + ap[j]) * w_a[j];
    for (int off = 4; off; off >>= 1)
        acc += __shfl_down_sync(0xffffffffu, acc, off, 8);
    __shared__ float sc[BSZ];
    if (jt == 0) sc[b] = acc;
    __syncthreads();
    if (t < 32) {
        float v = sc[t];
        float m = v;
        for (int off = 16; off; off >>= 1)
            m = fmaxf(m, __shfl_xor_sync(0xffffffffu, m, off));
        float e = expf(v - m);
        float ssum = e;
        for (int off = 16; off; off >>= 1)
            ssum += __shfl_xor_sync(0xffffffffu, ssum, off);
        float a = e / ssum;
        d_attnS[s * BSZ + t] = a;
        attn_out[s * BSZ + t] = a;
    }
}

// ------------- context = einsum('sb,sbe->be') into combined2[:,1620:3620] -------------
__global__ void k_context(const float* __restrict__ ann, int step)
{
    int i = blockIdx.x * blockDim.x + threadIdx.x;
    if (i >= BSZ * 2 * ECH) return;
    int b = i / (2 * ECH), e = i - b * (2 * ECH);
    float acc = 0.f;
#pragma unroll 5
    for (int s = 0; s < SRC; s++)
        acc += d_attnS[s * BSZ + b] * ann[(size_t)(s * BSZ + b) * (2 * ECH) + e];
    d_comb2[(size_t)(step * BSZ + b) * C2W + EMBED + DCH + e] = acc;
}

// ------------- GRU gates + h update; also stashes h_prev into combined2 -------------
__global__ void k_gates(int step, float* __restrict__ hidden_out)
{
    int i = blockIdx.x * blockDim.x + threadIdx.x;
    if (i >= BSZ * DCH) return;
    int b = i / DCH, j = i - b * DCH;
    const float* gi = d_gi + b * 3 * DCH;
    const float* gh = d_gh + b * 3 * DCH;
    float r = 1.f / (1.f + expf(-(gi[j] + gh[j])));
    float z = 1.f / (1.f + expf(-(gi[DCH + j] + gh[DCH + j])));
    float n = tanhf(gi[2 * DCH + j] + r * gh[2 * DCH + j]);
    float hp = d_hbuf[step & 1][i];
    float hn = (1.f - z) * n + z * hp;
    d_hbuf[(step + 1) & 1][i] = hn;
    d_comb2[(size_t)(step * BSZ + b) * C2W + EMBED + j] = hp;
    if (hidden_out) hidden_out[i] = hn;
}

// ------------- in-place log_softmax over vocab, one block per row -------------
__global__ __launch_bounds__(256) void k_lsm(float* __restrict__ logits)
{
    int m = blockIdx.x;
    float* row = logits + (size_t)m * VOCAB;
    int t = threadIdx.x;
    __shared__ float red[256];
    float mx = -1e30f;
    for (int v = t; v < VOCAB; v += 256) mx = fmaxf(mx, row[v]);
    red[t] = mx; __syncthreads();
    for (int s2 = 128; s2; s2 >>= 1) { if (t < s2) red[t] = fmaxf(red[t], red[t + s2]); __syncthreads(); }
    mx = red[0]; __syncthreads();
    float sum = 0.f;
    for (int v = t; v < VOCAB; v += 256) sum += expf(row[v] - mx);
    red[t] = sum; __syncthreads();
    for (int s2 = 128; s2; s2 >>= 1) { if (t < s2) red[t] += red[t + s2]; __syncthreads(); }
    float lse = mx + logf(red[0]);
    __syncthreads();
    for (int v = t; v < VOCAB; v += 256) row[v] -= lse;
}

// =================================================================================
extern "C" void kernel_launch(void* const* d_in, const int* in_sizes, int n_in,
                              void* d_out, int out_size)
{
    (void)in_sizes; (void)n_in; (void)out_size;
    const int*   tok  = (const int*)  d_in[0];
    const float* ann  = (const float*)d_in[1];
    const float* emb  = (const float*)d_in[2];
    const float* W_h  = (const float*)d_in[3];
    const float* b_h  = (const float*)d_in[4];
    const float* W_c  = (const float*)d_in[5];
    const float* b_c  = (const float*)d_in[6];
    const float* w_a  = (const float*)d_in[7];
    const float* W_ih = (const float*)d_in[8];
    const float* W_hh = (const float*)d_in[9];
    const float* b_ih = (const float*)d_in[10];
    const float* b_hh = (const float*)d_in[11];
    const float* W_p  = (const float*)d_in[12];
    const float* b_p  = (const float*)d_in[13];

    float* out    = (float*)d_out;
    float* preds  = out;                                 // (50,32,30000)
    float* hidden = out + (size_t)TRGN * BSZ * VOCAB;    // (1,32,1000)
    float* attns  = hidden + BSZ * DCH;                  // (50,50,32)

    float *annProj, *hbase, *hProj, *gi, *gh, *comb2, *giEmb;
    cudaGetSymbolAddress((void**)&annProj, d_annProj);
    cudaGetSymbolAddress((void**)&hbase,   d_hbuf);
    cudaGetSymbolAddress((void**)&hProj,   d_hProj);
    cudaGetSymbolAddress((void**)&gi,      d_gi);
    cudaGetSymbolAddress((void**)&gh,      d_gh);
    cudaGetSymbolAddress((void**)&comb2,   d_comb2);
    cudaGetSymbolAddress((void**)&giEmb,   d_giEmb);

    // 1) zero preds[0] (32*30000) and attns[0] (50*32)
    k_zero<<<(BSZ * VOCAB + 255) / 256, 256>>>(preds, attns, BSZ * VOCAB);

    // 2) gather embeddings for steps 0..48 into combined2[:,0:620]
    k_embed<<<(MROWS * EMBED + 255) / 256, 256>>>(tok, emb);

    // 3) h0 = tanh(ann[0,:,1000:2000] @ W_h.T + b_h)  -> hbuf[0]
    {
        dim3 g((DCH + 127) / 128, 1);
        k_sgemm<<<g, 256>>>(ann + ECH, 2 * ECH, W_h, ECH, b_h, nullptr, 0,
                            hbase, DCH, BSZ, DCH, ECH, 1);
    }
    // 4) annProj = ann(1600,2000) @ W_c[:,1000:].T + b_c
    {
        dim3 g((DCH + 127) / 128, (SRC * BSZ + 127) / 128);
        k_sgemm<<<g, 256>>>(ann, 2 * ECH, W_c + DCH, DCH + 2 * ECH, b_c, nullptr, 0,
                            annProj, DCH, SRC * BSZ, DCH, 2 * ECH, 0);
    }
    // 5) giEmb = emb_all(1568,620) @ W_ih[:,:620].T + b_ih
    {
        dim3 g((3 * DCH + 127) / 128, (MROWS + 127) / 128);
        k_sgemm<<<g, 256>>>(comb2, C2W, W_ih, EMBED + 2 * ECH, b_ih, nullptr, 0,
                            giEmb, 3 * DCH, MROWS, 3 * DCH, EMBED, 0);
    }

    // 6) sequential recurrence: 49 steps
    for (int i = 0; i < NSTEP; i++) {
        float* hcur = hbase + (i & 1) * (BSZ * DCH);
        // hProj = h @ W_c[:,:1000].T   (no bias; b_c already inside annProj)
        {
            dim3 g((DCH + 127) / 128, 1);
            k_sgemm<<<g, 256>>>(hcur, DCH, W_c, DCH + 2 * ECH, nullptr, nullptr, 0,
                                hProj, DCH, BSZ, DCH, DCH, 0);
        }
        // scores + softmax over batch axis -> attn scratch + attns output
        k_attn<<<SRC, 256>>>(w_a, attns + (size_t)(i + 1) * SRC * BSZ);
        // context -> combined2[:,1620:3620]
        k_context<<<(BSZ * 2 * ECH + 255) / 256, 256>>>(ann, i);
        // gi = giEmb[i] + ctx @ W_ih[:,620:].T
        {
            dim3 g((3 * DCH + 127) / 128, 1);
            k_sgemm<<<g, 256>>>(comb2 + (size_t)i * BSZ * C2W + EMBED + DCH, C2W,
                                W_ih + EMBED, EMBED + 2 * ECH, nullptr,
                                giEmb + (size_t)i * BSZ * 3 * DCH, 3 * DCH,
                                gi, 3 * DCH, BSZ, 3 * DCH, 2 * ECH, 0);
        }
        // gh = h @ W_hh.T + b_hh
        {
            dim3 g((3 * DCH + 127) / 128, 1);
            k_sgemm<<<g, 256>>>(hcur, DCH, W_hh, DCH, b_hh, nullptr, 0,
                                gh, 3 * DCH, BSZ, 3 * DCH, DCH, 0);
        }
        // gates + h update; stash h_prev into combined2[:,620:1620]
        k_gates<<<(BSZ * DCH + 255) / 256, 256>>>(i, (i == NSTEP - 1) ? hidden : nullptr);
    }

    // 7) big prediction GEMM: logits(1568,30000) = combined2 @ W_p.T + b_p
    //    written directly into preds rows 1..49
    {
        dim3 g((VOCAB + 127) / 128, (MROWS + 127) / 128);
        k_sgemm<<<g, 256>>>(comb2, C2W, W_p, C2W, b_p, nullptr, 0,
                            preds + (size_t)BSZ * VOCAB, VOCAB,
                            MROWS, VOCAB, C2W, 0);
    }
    // 8) in-place log_softmax
    k_lsm<<<MROWS, 256>>>(preds + (size_t)BSZ * VOCAB);
}

// round 3
// speedup vs baseline: 3.3448x; 3.3448x over previous
#include <cuda_runtime.h>
#include <cuda_bf16.h>
#include <mma.h>
#include <math.h>
#include <stdint.h>

using namespace nvcuda;

#define SRC 50
#define TRGN 50
#define BSZ 32
#define EMBED 620
#define ECH 1000
#define DCH 1000
#define VOCAB 30000
#define NSTEP 49
#define MROWS (NSTEP*BSZ)          /* 1568 */
#define KP_WP 3648                 /* 3620 padded to 64 */
#define KP_CTX 2048
#define KP_H 1024
#define KP_EMB 640
#define NGH 4000                   /* merged [W_hh | W_c1] output width */

// ============================ static scratch (bss, zero-initialized) ============================
__device__ __nv_bfloat16 d_WpH[(size_t)VOCAB*KP_WP], d_WpL[(size_t)VOCAB*KP_WP];
__device__ __nv_bfloat16 d_C2H[(size_t)MROWS*KP_WP], d_C2L[(size_t)MROWS*KP_WP];
__device__ __nv_bfloat16 d_annSH[(size_t)SRC*BSZ*KP_CTX], d_annSL[(size_t)SRC*BSZ*KP_CTX];
__device__ __nv_bfloat16 d_WhcH[(size_t)NGH*KP_H], d_WhcL[(size_t)NGH*KP_H];   // [W_hh(3000); W_c1(1000)]
__device__ __nv_bfloat16 d_Wc2H[(size_t)DCH*KP_CTX], d_Wc2L[(size_t)DCH*KP_CTX];
__device__ __nv_bfloat16 d_Wih1H[(size_t)3*DCH*KP_EMB], d_Wih1L[(size_t)3*DCH*KP_EMB];
__device__ __nv_bfloat16 d_Wih2H[(size_t)3*DCH*KP_CTX], d_Wih2L[(size_t)3*DCH*KP_CTX];
__device__ __nv_bfloat16 d_WhH[DCH*KP_H], d_WhL[DCH*KP_H];
__device__ __nv_bfloat16 d_EmbH[(size_t)MROWS*KP_EMB], d_EmbL[(size_t)MROWS*KP_EMB];
__device__ __nv_bfloat16 d_a0H[BSZ*KP_H], d_a0L[BSZ*KP_H];
__device__ __nv_bfloat16 d_hsH[2][BSZ*KP_H], d_hsL[2][BSZ*KP_H];
__device__ __nv_bfloat16 d_ctxH[BSZ*KP_CTX], d_ctxL[BSZ*KP_CTX];
__device__ float d_annProj[SRC*BSZ*DCH];
__device__ float d_hbuf[2][BSZ*DCH];
__device__ float d_ghp[BSZ*NGH];            // [gh(3000) | hProj(1000)] per batch row
__device__ float d_gi[BSZ*3*DCH];
__device__ float d_attnS[SRC*BSZ];
__device__ float d_giEmb[(size_t)MROWS*3*DCH];
__device__ float d_bcomb[NGH];

// ============================ WMMA bf16 split GEMM ============================
// C[M,N] = act( (Ah+Al) @ (Bh+Bl)^T + bias + Dadd ), dropping Al*Bl.
// A: [M,KP] lda, B: [N,KP] ldb (KP multiple of 32, zero-padded).
// Tile: BM x 128, K chunk 32. 8 warps / 256 threads.
template<int BM>
__global__ __launch_bounds__(256) void k_wgemm(
    const __nv_bfloat16* __restrict__ Ah, const __nv_bfloat16* __restrict__ Al, int lda,
    const __nv_bfloat16* __restrict__ Bh, const __nv_bfloat16* __restrict__ Bl, int ldb,
    const float* __restrict__ bias,
    const float* __restrict__ Dadd, int ldd,
    float* __restrict__ C, int ldc,
    int M, int N, int KP, int act)
{
    constexpr int MFR = (BM == 128) ? 2 : 1;   // 16-row frags per warp
    constexpr int NFR = (BM == 128) ? 4 : 2;   // 16-col frags per warp
    constexpr int AITEMS = BM * 4;             // uint4 per A tile
    constexpr int LDT = 48;                    // smem tile ld (bf16 elems), 96B rows (32B-mult)
    constexpr int LDC_S = 136;                 // smem epilogue ld (f32), 544B rows (32B-mult)

    extern __shared__ char smem[];
    __nv_bfloat16* As = (__nv_bfloat16*)smem;          // [BM][LDT]
    __nv_bfloat16* Bs = As + BM * LDT;                 // [128][LDT]
    float* Cs = (float*)smem;                          // [BM][LDC_S] (reuses tile space)

    const int tid = threadIdx.x, wid = tid >> 5;
    const int m0 = blockIdx.x * BM, n0 = blockIdx.y * 128;

    int wm, wn;
    if (BM == 128) { wm = wid & 3; wn = wid >> 2; }    // 4x2 warps, warp = 32x64
    else           { wm = wid & 1; wn = wid >> 1; }    // 2x4 warps, warp = 16x32
    const int wrow = wm * (16 * MFR);
    const int wcol = wn * (16 * NFR);

    wmma::fragment<wmma::accumulator, 16, 16, 16, float> acc[MFR][NFR];
#pragma unroll
    for (int i = 0; i < MFR; i++)
#pragma unroll
        for (int j = 0; j < NFR; j++)
            wmma::fill_fragment(acc[i][j], 0.0f);

    const int cpp = KP >> 5;      // 32-wide chunks per product
    const int total = 3 * cpp;    // products: AhBh, AhBl, AlBh

    uint4 pa[2], pb[2];
    auto fetch = [&](int c) {
        int p = c / cpp;
        int kc = (c - p * cpp) << 5;
        const __nv_bfloat16* Ap = (p < 2) ? Ah : Al;
        const __nv_bfloat16* Bp = (p == 1) ? Bl : Bh;
#pragma unroll
        for (int q = 0; q < (BM == 128 ? 2 : 1); q++) {
            int it = tid + q * 256;
            if (BM == 32 && it >= AITEMS) { pa[q] = make_uint4(0,0,0,0); continue; }
            int r = it >> 2, seg = it & 3;
            int gm = m0 + r;
            pa[q] = (gm < M) ? *(const uint4*)(Ap + (size_t)gm * lda + kc + seg * 8)
                             : make_uint4(0,0,0,0);
        }
#pragma unroll
        for (int q = 0; q < 2; q++) {
            int it = tid + q * 256;
            int r = it >> 2, seg = it & 3;
            int gn = n0 + r;
            pb[q] = (gn < N) ? *(const uint4*)(Bp + (size_t)gn * ldb + kc + seg * 8)
                             : make_uint4(0,0,0,0);
        }
    };
    fetch(0);

    for (int c = 0; c < total; c++) {
        // commit prefetched regs to smem
#pragma unroll
        for (int q = 0; q < (BM == 128 ? 2 : 1); q++) {
            int it = tid + q * 256;
            if (BM == 32 && it >= AITEMS) continue;
            int r = it >> 2, seg = it & 3;
            *(uint4*)(As + r * LDT + seg * 8) = pa[q];
        }
#pragma unroll
        for (int q = 0; q < 2; q++) {
            int it = tid + q * 256;
            int r = it >> 2, seg = it & 3;
            *(uint4*)(Bs + r * LDT + seg * 8) = pb[q];
        }
        __syncthreads();
        if (c + 1 < total) fetch(c + 1);   // overlap next-chunk global loads with MMA
#pragma unroll
        for (int kk = 0; kk < 32; kk += 16) {
            wmma::fragment<wmma::matrix_a, 16,16,16, __nv_bfloat16, wmma::row_major> af[MFR];
            wmma::fragment<wmma::matrix_b, 16,16,16, __nv_bfloat16, wmma::col_major> bf[NFR];
#pragma unroll
            for (int i = 0; i < MFR; i++)
                wmma::load_matrix_sync(af[i], As + (wrow + i * 16) * LDT + kk, LDT);
#pragma unroll
            for (int j = 0; j < NFR; j++)
                wmma::load_matrix_sync(bf[j], Bs + (wcol + j * 16) * LDT + kk, LDT);
#pragma unroll
            for (int i = 0; i < MFR; i++)
#pragma unroll
                for (int j = 0; j < NFR; j++)
                    wmma::mma_sync(acc[i][j], af[i], bf[j], acc[i][j]);
        }
        __syncthreads();
    }

    // epilogue: frags -> smem -> global with bias/Dadd/act
#pragma unroll
    for (int i = 0; i < MFR; i++)
#pragma unroll
        for (int j = 0; j < NFR; j++)
            wmma::store_matrix_sync(Cs + (wrow + i * 16) * LDC_S + wcol + j * 16,
                                    acc[i][j], LDC_S, wmma::mem_row_major);
    __syncthreads();
    for (int idx = tid; idx < BM * 128; idx += 256) {
        int r = idx >> 7, cc = idx & 127;
        int gm = m0 + r, gn = n0 + cc;
        if (gm < M && gn < N) {
            float v = Cs[r * LDC_S + cc];
            if (bias) v += bias[gn];
            if (Dadd) v += Dadd[(size_t)gm * ldd + gn];
            if (act)  v = tanhf(v);
            C[(size_t)gm * ldc + gn] = v;
        }
    }
}

// ============================ small kernels ============================
__global__ void k_split(const float* __restrict__ src, int sld, int colOff, int rows, int cols,
                        __nv_bfloat16* __restrict__ hi, __nv_bfloat16* __restrict__ lo, int dld)
{
    int i = blockIdx.x * blockDim.x + threadIdx.x;
    if (i >= rows * dld) return;
    int r = i / dld, c = i - r * dld;
    float x = (c < cols) ? src[(size_t)r * sld + colOff + c] : 0.f;
    __nv_bfloat16 h = __float2bfloat16(x);
    hi[i] = h;
    lo[i] = __float2bfloat16(x - __bfloat162float(h));
}

__global__ void k_zero(float* __restrict__ preds0, float* __restrict__ attns0, int n)
{
    int i = blockIdx.x * blockDim.x + threadIdx.x;
    if (i < n) preds0[i] = 0.f;
    if (i < SRC * BSZ) attns0[i] = 0.f;
}

__global__ void k_bcomb(const float* __restrict__ b_hh)
{
    int i = blockIdx.x * blockDim.x + threadIdx.x;
    if (i < NGH) d_bcomb[i] = (i < 3 * DCH) ? b_hh[i] : 0.f;
}

// gather embeddings; split into EmbS [0,640) and comb2 cols [0,620)
__global__ void k_embedS(const int* __restrict__ tok, const float* __restrict__ emb)
{
    int i = blockIdx.x * blockDim.x + threadIdx.x;
    if (i >= MROWS * KP_EMB) return;
    int m = i / KP_EMB, e = i - m * KP_EMB;
    float x = (e < EMBED) ? emb[(size_t)tok[m] * EMBED + e] : 0.f;
    __nv_bfloat16 h = __float2bfloat16(x);
    __nv_bfloat16 l = __float2bfloat16(x - __bfloat162float(h));
    d_EmbH[i] = h; d_EmbL[i] = l;
    if (e < EMBED) {
        size_t o = (size_t)m * KP_WP + e;
        d_C2H[o] = h; d_C2L[o] = l;
    }
}

// attention scores + softmax over BATCH axis (faithful to reference)
__global__ void k_attn(const float* __restrict__ w_a, float* __restrict__ attn_out)
{
    int s = blockIdx.x;
    int t = threadIdx.x;
    int b = t >> 3, jt = t & 7;
    const float* hp = d_ghp + b * NGH + 3 * DCH;   // hProj slice
    const float* ap = d_annProj + (size_t)(s * BSZ + b) * DCH;
    float acc = 0.f;
    for (int j = jt; j < DCH; j += 8)
        acc += tanhf(hp[j] + ap[j]) * w_a[j];
    for (int off = 4; off; off >>= 1)
        acc += __shfl_down_sync(0xffffffffu, acc, off, 8);
    __shared__ float sc[BSZ];
    if (jt == 0) sc[b] = acc;
    __syncthreads();
    if (t < 32) {
        float v = sc[t];
        float m = v;
        for (int off = 16; off; off >>= 1) m = fmaxf(m, __shfl_xor_sync(0xffffffffu, m, off));
        float e = expf(v - m);
        float ssum = e;
        for (int off = 16; off; off >>= 1) ssum += __shfl_xor_sync(0xffffffffu, ssum, off);
        float a = e / ssum;
        d_attnS[s * BSZ + t] = a;
        attn_out[s * BSZ + t] = a;
    }
}

// context; split into ctx buffer and comb2 cols [1620,3620)
__global__ void k_context(const float* __restrict__ ann, int step)
{
    int i = blockIdx.x * blockDim.x + threadIdx.x;
    if (i >= BSZ * 2 * ECH) return;
    int b = i / (2 * ECH), e = i - b * (2 * ECH);
    float acc = 0.f;
#pragma unroll 5
    for (int s = 0; s < SRC; s++)
        acc += d_attnS[s * BSZ + b] * ann[(size_t)(s * BSZ + b) * (2 * ECH) + e];
    __nv_bfloat16 h = __float2bfloat16(acc);
    __nv_bfloat16 l = __float2bfloat16(acc - __bfloat162float(h));
    d_ctxH[b * KP_CTX + e] = h; d_ctxL[b * KP_CTX + e] = l;
    size_t o = (size_t)(step * BSZ + b) * KP_WP + EMBED + DCH + e;
    d_C2H[o] = h; d_C2L[o] = l;
}

// GRU gates + h update; stashes h_prev split into comb2, h_new split for next step
__global__ void k_gates(int step, float* __restrict__ hidden_out)
{
    int i = blockIdx.x * blockDim.x + threadIdx.x;
    if (i >= BSZ * DCH) return;
    int b = i / DCH, j = i - b * DCH;
    const float* gi = d_gi + b * 3 * DCH;
    const float* gh = d_ghp + b * NGH;
    float r = 1.f / (1.f + expf(-(gi[j] + gh[j])));
    float z = 1.f / (1.f + expf(-(gi[DCH + j] + gh[DCH + j])));
    float n = tanhf(gi[2 * DCH + j] + r * gh[2 * DCH + j]);
    float hp = d_hbuf[step & 1][i];
    float hn = (1.f - z) * n + z * hp;
    d_hbuf[(step + 1) & 1][i] = hn;
    __nv_bfloat16 hh = __float2bfloat16(hn);
    d_hsH[(step + 1) & 1][b * KP_H + j] = hh;
    d_hsL[(step + 1) & 1][b * KP_H + j] = __float2bfloat16(hn - __bfloat162float(hh));
    __nv_bfloat16 ph = __float2bfloat16(hp);
    size_t o = (size_t)(step * BSZ + b) * KP_WP + EMBED + j;
    d_C2H[o] = ph;
    d_C2L[o] = __float2bfloat16(hp - __bfloat162float(ph));
    if (hidden_out) hidden_out[i] = hn;
}

// in-place log_softmax over vocab
__global__ __launch_bounds__(256) void k_lsm(float* __restrict__ logits)
{
    int m = blockIdx.x;
    float* row = logits + (size_t)m * VOCAB;
    int t = threadIdx.x;
    __shared__ float red[256];
    float mx = -1e30f;
    for (int v = t; v < VOCAB; v += 256) mx = fmaxf(mx, row[v]);
    red[t] = mx; __syncthreads();
    for (int s2 = 128; s2; s2 >>= 1) { if (t < s2) red[t] = fmaxf(red[t], red[t + s2]); __syncthreads(); }
    mx = red[0]; __syncthreads();
    float sum = 0.f;
    for (int v = t; v < VOCAB; v += 256) sum += expf(row[v] - mx);
    red[t] = sum; __syncthreads();
    for (int s2 = 128; s2; s2 >>= 1) { if (t < s2) red[t] += red[t + s2]; __syncthreads(); }
    float lse = mx + logf(red[0]);
    __syncthreads();
    for (int v = t; v < VOCAB; v += 256) row[v] -= lse;
}

// ============================ host ============================
#define SYM(p, s) do { void* _t; cudaGetSymbolAddress(&_t, s); p = (decltype(p))_t; } while (0)

#define SMEM_G128 (128 * 136 * 4)   /* 69632: epilogue dominates */
#define SMEM_G32  (32 * 136 * 4)    /* 17408 >= tile region 15360 */

static inline void g128(const __nv_bfloat16* Ah, const __nv_bfloat16* Al, int lda,
                        const __nv_bfloat16* Bh, const __nv_bfloat16* Bl, int ldb,
                        const float* bias, const float* Dadd, int ldd,
                        float* C, int ldc, int M, int N, int KP, int act)
{
    dim3 g((M + 127) / 128, (N + 127) / 128);
    k_wgemm<128><<<g, 256, SMEM_G128>>>(Ah, Al, lda, Bh, Bl, ldb, bias, Dadd, ldd, C, ldc, M, N, KP, act);
}
static inline void g32(const __nv_bfloat16* Ah, const __nv_bfloat16* Al, int lda,
                       const __nv_bfloat16* Bh, const __nv_bfloat16* Bl, int ldb,
                       const float* bias, const float* Dadd, int ldd,
                       float* C, int ldc, int M, int N, int KP, int act)
{
    dim3 g((M + 31) / 32, (N + 127) / 128);
    k_wgemm<32><<<g, 256, SMEM_G32>>>(Ah, Al, lda, Bh, Bl, ldb, bias, Dadd, ldd, C, ldc, M, N, KP, act);
}

extern "C" void kernel_launch(void* const* d_in, const int* in_sizes, int n_in,
                              void* d_out, int out_size)
{
    (void)in_sizes; (void)n_in; (void)out_size;
    const int*   tok  = (const int*)  d_in[0];
    const float* ann  = (const float*)d_in[1];
    const float* emb  = (const float*)d_in[2];
    const float* W_h  = (const float*)d_in[3];
    const float* b_h  = (const float*)d_in[4];
    const float* W_c  = (const float*)d_in[5];
    const float* b_c  = (const float*)d_in[6];
    const float* w_a  = (const float*)d_in[7];
    const float* W_ih = (const float*)d_in[8];
    const float* W_hh = (const float*)d_in[9];
    const float* b_ih = (const float*)d_in[10];
    const float* b_hh = (const float*)d_in[11];
    const float* W_p  = (const float*)d_in[12];
    const float* b_p  = (const float*)d_in[13];

    float* out    = (float*)d_out;
    float* preds  = out;
    float* hidden = out + (size_t)TRGN * BSZ * VOCAB;
    float* attns  = hidden + BSZ * DCH;

    static bool attrDone = false;
    if (!attrDone) {
        cudaFuncSetAttribute(k_wgemm<128>, cudaFuncAttributeMaxDynamicSharedMemorySize, SMEM_G128);
        cudaFuncSetAttribute(k_wgemm<32>,  cudaFuncAttributeMaxDynamicSharedMemorySize, SMEM_G32);
        attrDone = true;
    }

    __nv_bfloat16 *WpH,*WpL,*C2H,*C2L,*annSH,*annSL,*WhcH,*WhcL,*Wc2H,*Wc2L;
    __nv_bfloat16 *Wih1H,*Wih1L,*Wih2H,*Wih2L,*WhH,*WhL,*EmbH,*EmbL;
    __nv_bfloat16 *a0H,*a0L,*hsH,*hsL,*ctxH,*ctxL;
    float *annProj,*hbase,*ghp,*gi,*giEmb,*bcomb;
    SYM(WpH, d_WpH);   SYM(WpL, d_WpL);
    SYM(C2H, d_C2H);   SYM(C2L, d_C2L);
    SYM(annSH, d_annSH); SYM(annSL, d_annSL);
    SYM(WhcH, d_WhcH); SYM(WhcL, d_WhcL);
    SYM(Wc2H, d_Wc2H); SYM(Wc2L, d_Wc2L);
    SYM(Wih1H, d_Wih1H); SYM(Wih1L, d_Wih1L);
    SYM(Wih2H, d_Wih2H); SYM(Wih2L, d_Wih2L);
    SYM(WhH, d_WhH);   SYM(WhL, d_WhL);
    SYM(EmbH, d_EmbH); SYM(EmbL, d_EmbL);
    SYM(a0H, d_a0H);   SYM(a0L, d_a0L);
    SYM(hsH, d_hsH);   SYM(hsL, d_hsL);
    SYM(ctxH, d_ctxH); SYM(ctxL, d_ctxL);
    SYM(annProj, d_annProj); SYM(hbase, d_hbuf);
    SYM(ghp, d_ghp); SYM(gi, d_gi); SYM(giEmb, d_giEmb);
    SYM(bcomb, d_bcomb);

    const int C2W = EMBED + DCH + 2 * ECH;   // 3620
    const int WIHW = EMBED + 2 * ECH;        // 2620

    // ---- conversions ----
    auto split = [](const float* s, int sld, int off, int rows, int cols,
                    __nv_bfloat16* hi, __nv_bfloat16* lo, int dld) {
        long long tot = (long long)rows * dld;
        k_split<<<(unsigned)((tot + 255) / 256), 256>>>(s, sld, off, rows, cols, hi, lo, dld);
    };
    split(W_p, C2W, 0, VOCAB, C2W, WpH, WpL, KP_WP);
    split(W_hh, DCH, 0, 3 * DCH, DCH, WhcH, WhcL, KP_H);                       // rows 0..2999
    split(W_c, DCH + 2 * ECH, 0, DCH, DCH, WhcH + (size_t)3*DCH*KP_H,
          WhcL + (size_t)3*DCH*KP_H, KP_H);                                    // rows 3000..3999 = W_c1
    split(W_c, DCH + 2 * ECH, DCH, DCH, 2 * ECH, Wc2H, Wc2L, KP_CTX);
    split(W_ih, WIHW, 0,     3 * DCH, EMBED,   Wih1H, Wih1L, KP_EMB);
    split(W_ih, WIHW, EMBED, 3 * DCH, 2 * ECH, Wih2H, Wih2L, KP_CTX);
    split(W_h, ECH, 0, DCH, ECH, WhH, WhL, KP_H);
    split(ann, 2 * ECH, 0,   SRC * BSZ, 2 * ECH, annSH, annSL, KP_CTX);
    split(ann, 2 * ECH, ECH, BSZ, ECH, a0H, a0L, KP_H);
    k_bcomb<<<(NGH + 255) / 256, 256>>>(b_hh);
    k_zero<<<(BSZ * VOCAB + 255) / 256, 256>>>(preds, attns, BSZ * VOCAB);
    k_embedS<<<(MROWS * KP_EMB + 255) / 256, 256>>>(tok, emb);

    // ---- h0 = tanh(ann0_bw @ W_h^T + b_h) ----
    g32(a0H, a0L, KP_H, WhH, WhL, KP_H, b_h, nullptr, 0, hbase, DCH, BSZ, DCH, KP_H, 1);
    k_split<<<(BSZ * KP_H + 255) / 256, 256>>>(hbase, DCH, 0, BSZ, DCH, hsH, hsL, KP_H);

    // ---- annProj = ann @ W_c2^T + b_c ----
    g128(annSH, annSL, KP_CTX, Wc2H, Wc2L, KP_CTX, b_c, nullptr, 0,
         annProj, DCH, SRC * BSZ, DCH, KP_CTX, 0);
    // ---- giEmb = embedded @ W_ih1^T + b_ih ----
    g128(EmbH, EmbL, KP_EMB, Wih1H, Wih1L, KP_EMB, b_ih, nullptr, 0,
         giEmb, 3 * DCH, MROWS, 3 * DCH, KP_EMB, 0);

    // ---- 49-step recurrence ----
    for (int i = 0; i < NSTEP; i++) {
        const __nv_bfloat16* hH = hsH + (i & 1) * (BSZ * KP_H);
        const __nv_bfloat16* hL = hsL + (i & 1) * (BSZ * KP_H);
        // [gh | hProj] = h @ [W_hh; W_c1]^T + [b_hh; 0]
        g32(hH, hL, KP_H, WhcH, WhcL, KP_H, bcomb, nullptr, 0,
            ghp, NGH, BSZ, NGH, KP_H, 0);
        k_attn<<<SRC, 256>>>(w_a, attns + (size_t)(i + 1) * SRC * BSZ);
        k_context<<<(BSZ * 2 * ECH + 255) / 256, 256>>>(ann, i);
        // gi = ctx @ W_ih2^T + giEmb[i]   (b_ih already in giEmb)
        g32(ctxH, ctxL, KP_CTX, Wih2H, Wih2L, KP_CTX, nullptr,
            giEmb + (size_t)i * BSZ * 3 * DCH, 3 * DCH,
            gi, 3 * DCH, BSZ, 3 * DCH, KP_CTX, 0);
        k_gates<<<(BSZ * DCH + 255) / 256, 256>>>(i, (i == NSTEP - 1) ? hidden : nullptr);
    }

    // ---- big prediction GEMM straight into preds rows 1..49 ----
    g128(C2H, C2L, KP_WP, WpH, WpL, KP_WP, b_p, nullptr, 0,
         preds + (size_t)BSZ * VOCAB, VOCAB, MROWS, VOCAB, KP_WP, 0);
    k_lsm<<<MROWS, 256>>>(preds + (size_t)BSZ * VOCAB);
}

// round 4
// speedup vs baseline: 5.0706x; 1.5160x over previous
#include <cuda_runtime.h>
#include <cuda_bf16.h>
#include <mma.h>
#include <math.h>
#include <stdint.h>

using namespace nvcuda;

#define SRC 50
#define TRGN 50
#define BSZ 32
#define EMBED 620
#define ECH 1000
#define DCH 1000
#define VOCAB 30000
#define NSTEP 49
#define MROWS (NSTEP*BSZ)          /* 1568 */
#define KP_WP 3648                 /* 3620 padded to 64 */
#define KP_CTX 2048
#define KP_H 1024
#define KP_EMB 640
#define NGH 4000                   /* merged [W_hh | W_c1] output width */

// ============================ static scratch (bss, zero-initialized) ============================
__device__ __nv_bfloat16 d_WpH[(size_t)VOCAB*KP_WP], d_WpL[(size_t)VOCAB*KP_WP];
__device__ __nv_bfloat16 d_C2H[(size_t)MROWS*KP_WP], d_C2L[(size_t)MROWS*KP_WP];
__device__ __nv_bfloat16 d_annSH[(size_t)SRC*BSZ*KP_CTX], d_annSL[(size_t)SRC*BSZ*KP_CTX];
__device__ __nv_bfloat16 d_WhcH[(size_t)NGH*KP_H], d_WhcL[(size_t)NGH*KP_H];   // [W_hh(3000); W_c1(1000)]
__device__ __nv_bfloat16 d_Wc2H[(size_t)DCH*KP_CTX], d_Wc2L[(size_t)DCH*KP_CTX];
__device__ __nv_bfloat16 d_Wih1H[(size_t)3*DCH*KP_EMB], d_Wih1L[(size_t)3*DCH*KP_EMB];
__device__ __nv_bfloat16 d_Wih2H[(size_t)3*DCH*KP_CTX], d_Wih2L[(size_t)3*DCH*KP_CTX];
__device__ __nv_bfloat16 d_WhH[DCH*KP_H], d_WhL[DCH*KP_H];
__device__ __nv_bfloat16 d_EmbH[(size_t)MROWS*KP_EMB], d_EmbL[(size_t)MROWS*KP_EMB];
__device__ __nv_bfloat16 d_a0H[BSZ*KP_H], d_a0L[BSZ*KP_H];
__device__ __nv_bfloat16 d_hsH[2][BSZ*KP_H], d_hsL[2][BSZ*KP_H];
__device__ float d_annProj[SRC*BSZ*DCH];
__device__ float d_annIh[(size_t)SRC*BSZ*3*DCH];   // ann @ W_ih2^T  (19.2 MB)
__device__ float d_hbuf[2][BSZ*DCH];
__device__ float d_ghp[BSZ*NGH];            // [gh(3000) | hProj(1000)] per batch row
__device__ float d_attnS[SRC*BSZ];
__device__ float d_giEmb[(size_t)MROWS*3*DCH];
__device__ float d_bcomb[NGH];

// ============================ cp.async helpers ============================
__device__ __forceinline__ uint32_t smem_u32(const void* p) {
    uint32_t a;
    asm("{ .reg .u64 t; cvta.to.shared.u64 t, %1; cvt.u32.u64 %0, t; }" : "=r"(a) : "l"(p));
    return a;
}
__device__ __forceinline__ void cp_async16(uint32_t dst, const void* src) {
    asm volatile("cp.async.cg.shared.global [%0], [%1], 16;\n" :: "r"(dst), "l"(src));
}
__device__ __forceinline__ void cp_commit() {
    asm volatile("cp.async.commit_group;\n" ::: "memory");
}

// ============================ WMMA bf16 split GEMM (2-stage cp.async pipeline) ============================
// C[M,N] = act( (Ah+Al) @ (Bh+Bl)^T + bias + Dadd ), dropping Al*Bl.
// A: [M,KP] lda, B: [N,KP] ldb (KP multiple of 32, zero-padded).
template<int BM>
__global__ __launch_bounds__(256) void k_wgemm(
    const __nv_bfloat16* __restrict__ Ah, const __nv_bfloat16* __restrict__ Al, int lda,
    const __nv_bfloat16* __restrict__ Bh, const __nv_bfloat16* __restrict__ Bl, int ldb,
    const float* __restrict__ bias,
    const float* __restrict__ Dadd, int ldd,
    float* __restrict__ C, int ldc,
    int M, int N, int KP, int act)
{
    constexpr int MFR = (BM == 128) ? 2 : 1;
    constexpr int NFR = (BM == 128) ? 4 : 2;
    constexpr int AITEMS = BM * 4;             // uint4 per A tile
    constexpr int LDT = 48;                    // smem tile ld (bf16), 96B rows
    constexpr int LDC_S = 136;                 // epilogue ld (f32)
    constexpr int STAGE = (BM + 128) * LDT;    // bf16 elems per stage

    extern __shared__ char smem[];
    __nv_bfloat16* tiles = (__nv_bfloat16*)smem;   // [2][STAGE]
    float* Cs = (float*)smem;                      // epilogue reuse

    const int tid = threadIdx.x, wid = tid >> 5;
    const int m0 = blockIdx.x * BM, n0 = blockIdx.y * 128;

    int wm, wn;
    if (BM == 128) { wm = wid & 3; wn = wid >> 2; }
    else           { wm = wid & 1; wn = wid >> 1; }
    const int wrow = wm * (16 * MFR);
    const int wcol = wn * (16 * NFR);

    wmma::fragment<wmma::accumulator, 16, 16, 16, float> acc[MFR][NFR];
#pragma unroll
    for (int i = 0; i < MFR; i++)
#pragma unroll
        for (int j = 0; j < NFR; j++)
            wmma::fill_fragment(acc[i][j], 0.0f);

    const int cpp = KP >> 5;
    const int total = 3 * cpp;     // AhBh, AhBl, AlBh

    auto prefetch = [&](int c, int stage) {
        int p = c / cpp;
        int kc = (c - p * cpp) << 5;
        const __nv_bfloat16* Ap = (p < 2) ? Ah : Al;
        const __nv_bfloat16* Bp = (p == 1) ? Bl : Bh;
        __nv_bfloat16* As = tiles + stage * STAGE;
        __nv_bfloat16* Bs = As + BM * LDT;
#pragma unroll
        for (int q = 0; q < (BM == 128 ? 2 : 1); q++) {
            int it = tid + q * 256;
            if (BM == 32 && it >= AITEMS) break;
            int r = it >> 2, seg = it & 3;
            int gm = m0 + r; if (gm >= M) gm = M - 1;   // clamp (finite garbage, masked in epilogue)
            cp_async16(smem_u32(As + r * LDT + seg * 8), Ap + (size_t)gm * lda + kc + seg * 8);
        }
#pragma unroll
        for (int q = 0; q < 2; q++) {
            int it = tid + q * 256;
            int r = it >> 2, seg = it & 3;
            int gn = n0 + r; if (gn >= N) gn = N - 1;
            cp_async16(smem_u32(Bs + r * LDT + seg * 8), Bp + (size_t)gn * ldb + kc + seg * 8);
        }
        cp_commit();
    };

    prefetch(0, 0);
    prefetch(1, 1);

    for (int c = 0; c < total; c++) {
        if (c + 1 < total) { asm volatile("cp.async.wait_group 1;\n" ::: "memory"); }
        else               { asm volatile("cp.async.wait_group 0;\n" ::: "memory"); }
        __syncthreads();
        const __nv_bfloat16* As = tiles + (c & 1) * STAGE;
        const __nv_bfloat16* Bs = As + BM * LDT;
#pragma unroll
        for (int kk = 0; kk < 32; kk += 16) {
            wmma::fragment<wmma::matrix_a, 16,16,16, __nv_bfloat16, wmma::row_major> af[MFR];
            wmma::fragment<wmma::matrix_b, 16,16,16, __nv_bfloat16, wmma::col_major> bf[NFR];
#pragma unroll
            for (int i = 0; i < MFR; i++)
                wmma::load_matrix_sync(af[i], As + (wrow + i * 16) * LDT + kk, LDT);
#pragma unroll
            for (int j = 0; j < NFR; j++)
                wmma::load_matrix_sync(bf[j], Bs + (wcol + j * 16) * LDT + kk, LDT);
#pragma unroll
            for (int i = 0; i < MFR; i++)
#pragma unroll
                for (int j = 0; j < NFR; j++)
                    wmma::mma_sync(acc[i][j], af[i], bf[j], acc[i][j]);
        }
        __syncthreads();
        if (c + 2 < total) prefetch(c + 2, c & 1);
    }

    // epilogue: frags -> smem -> global with bias/Dadd/act
#pragma unroll
    for (int i = 0; i < MFR; i++)
#pragma unroll
        for (int j = 0; j < NFR; j++)
            wmma::store_matrix_sync(Cs + (wrow + i * 16) * LDC_S + wcol + j * 16,
                                    acc[i][j], LDC_S, wmma::mem_row_major);
    __syncthreads();
    for (int idx = tid; idx < BM * 128; idx += 256) {
        int r = idx >> 7, cc = idx & 127;
        int gm = m0 + r, gn = n0 + cc;
        if (gm < M && gn < N) {
            float v = Cs[r * LDC_S + cc];
            if (bias) v += bias[gn];
            if (Dadd) v += Dadd[(size_t)gm * ldd + gn];
            if (act)  v = tanhf(v);
            C[(size_t)gm * ldc + gn] = v;
        }
    }
}

// ============================ small kernels ============================
__global__ void k_split(const float* __restrict__ src, int sld, int colOff, int rows, int cols,
                        __nv_bfloat16* __restrict__ hi, __nv_bfloat16* __restrict__ lo, int dld)
{
    int i = blockIdx.x * blockDim.x + threadIdx.x;
    if (i >= rows * dld) return;
    int r = i / dld, c = i - r * dld;
    float x = (c < cols) ? src[(size_t)r * sld + colOff + c] : 0.f;
    __nv_bfloat16 h = __float2bfloat16(x);
    hi[i] = h;
    lo[i] = __float2bfloat16(x - __bfloat162float(h));
}

__global__ void k_zero(float* __restrict__ preds0, float* __restrict__ attns0, int n)
{
    int i = blockIdx.x * blockDim.x + threadIdx.x;
    if (i < n) preds0[i] = 0.f;
    if (i < SRC * BSZ) attns0[i] = 0.f;
}

__global__ void k_bcomb(const float* __restrict__ b_hh)
{
    int i = blockIdx.x * blockDim.x + threadIdx.x;
    if (i < NGH) d_bcomb[i] = (i < 3 * DCH) ? b_hh[i] : 0.f;
}

// gather embeddings; split into EmbS [0,640) and comb2 cols [0,620)
__global__ void k_embedS(const int* __restrict__ tok, const float* __restrict__ emb)
{
    int i = blockIdx.x * blockDim.x + threadIdx.x;
    if (i >= MROWS * KP_EMB) return;
    int m = i / KP_EMB, e = i - m * KP_EMB;
    float x = (e < EMBED) ? emb[(size_t)tok[m] * EMBED + e] : 0.f;
    __nv_bfloat16 h = __float2bfloat16(x);
    __nv_bfloat16 l = __float2bfloat16(x - __bfloat162float(h));
    d_EmbH[i] = h; d_EmbL[i] = l;
    if (e < EMBED) {
        size_t o = (size_t)m * KP_WP + e;
        d_C2H[o] = h; d_C2L[o] = l;
    }
}

// attention scores + softmax over BATCH axis (faithful to reference)
__global__ void k_attn(const float* __restrict__ w_a, float* __restrict__ attn_out)
{
    int s = blockIdx.x;
    int t = threadIdx.x;
    int b = t >> 3, jt = t & 7;
    const float* hp = d_ghp + b * NGH + 3 * DCH;   // hProj slice
    const float* ap = d_annProj + (size_t)(s * BSZ + b) * DCH;
    float acc = 0.f;
    for (int j = jt; j < DCH; j += 8)
        acc += tanhf(hp[j] + ap[j]) * w_a[j];
    for (int off = 4; off; off >>= 1)
        acc += __shfl_down_sync(0xffffffffu, acc, off, 8);
    __shared__ float sc[BSZ];
    if (jt == 0) sc[b] = acc;
    __syncthreads();
    if (t < 32) {
        float v = sc[t];
        float m = v;
        for (int off = 16; off; off >>= 1) m = fmaxf(m, __shfl_xor_sync(0xffffffffu, m, off));
        float e = expf(v - m);
        float ssum = e;
        for (int off = 16; off; off >>= 1) ssum += __shfl_xor_sync(0xffffffffu, ssum, off);
        float a = e / ssum;
        d_attnS[s * BSZ + t] = a;
        attn_out[s * BSZ + t] = a;
    }
}

// fused: context (-> comb2 split), gi = giEmb + Sum_s attn*annIh, GRU gates, h update.
// One block per batch row b.
__global__ __launch_bounds__(256) void k_fuse(const float* __restrict__ ann, int step,
                                              float* __restrict__ hidden_out)
{
    const int b = blockIdx.x;
    const int t = threadIdx.x;
    __shared__ float sat[SRC];
    __shared__ float sgi[3 * DCH];
    if (t < SRC) sat[t] = d_attnS[t * BSZ + b];
    __syncthreads();

    // context -> comb2 cols [1620,3620) split
    for (int e = t; e < 2 * ECH; e += 256) {
        float acc = 0.f;
        const float* ap = ann + (size_t)b * (2 * ECH) + e;
#pragma unroll 10
        for (int s = 0; s < SRC; s++)
            acc += sat[s] * ap[(size_t)s * BSZ * (2 * ECH)];
        __nv_bfloat16 h = __float2bfloat16(acc);
        size_t o = (size_t)(step * BSZ + b) * KP_WP + EMBED + DCH + e;
        d_C2H[o] = h;
        d_C2L[o] = __float2bfloat16(acc - __bfloat162float(h));
    }
    // gi = giEmb[step,b] + Sum_s attn * annIh[s,b]
    const float* gE = d_giEmb + ((size_t)step * BSZ + b) * 3 * DCH;
    for (int j = t; j < 3 * DCH; j += 256) {
        float acc = gE[j];
        const float* ip = d_annIh + (size_t)b * 3 * DCH + j;
#pragma unroll 10
        for (int s = 0; s < SRC; s++)
            acc += sat[s] * ip[(size_t)s * BSZ * 3 * DCH];
        sgi[j] = acc;
    }
    __syncthreads();

    // gates
    const float* gh = d_ghp + b * NGH;
    for (int j = t; j < DCH; j += 256) {
        float r = 1.f / (1.f + expf(-(sgi[j] + gh[j])));
        float z = 1.f / (1.f + expf(-(sgi[DCH + j] + gh[DCH + j])));
        float n = tanhf(sgi[2 * DCH + j] + r * gh[2 * DCH + j]);
        float hp = d_hbuf[step & 1][b * DCH + j];
        float hn = (1.f - z) * n + z * hp;
        d_hbuf[(step + 1) & 1][b * DCH + j] = hn;
        __nv_bfloat16 hh = __float2bfloat16(hn);
        d_hsH[(step + 1) & 1][b * KP_H + j] = hh;
        d_hsL[(step + 1) & 1][b * KP_H + j] = __float2bfloat16(hn - __bfloat162float(hh));
        __nv_bfloat16 ph = __float2bfloat16(hp);
        size_t o = (size_t)(step * BSZ + b) * KP_WP + EMBED + j;
        d_C2H[o] = ph;
        d_C2L[o] = __float2bfloat16(hp - __bfloat162float(ph));
        if (hidden_out) hidden_out[b * DCH + j] = hn;
    }
}

// in-place log_softmax over vocab
__global__ __launch_bounds__(256) void k_lsm(float* __restrict__ logits)
{
    int m = blockIdx.x;
    float* row = logits + (size_t)m * VOCAB;
    int t = threadIdx.x;
    __shared__ float red[256];
    float mx = -1e30f;
    for (int v = t; v < VOCAB; v += 256) mx = fmaxf(mx, row[v]);
    red[t] = mx; __syncthreads();
    for (int s2 = 128; s2; s2 >>= 1) { if (t < s2) red[t] = fmaxf(red[t], red[t + s2]); __syncthreads(); }
    mx = red[0]; __syncthreads();
    float sum = 0.f;
    for (int v = t; v < VOCAB; v += 256) sum += expf(row[v] - mx);
    red[t] = sum; __syncthreads();
    for (int s2 = 128; s2; s2 >>= 1) { if (t < s2) red[t] += red[t + s2]; __syncthreads(); }
    float lse = mx + logf(red[0]);
    __syncthreads();
    for (int v = t; v < VOCAB; v += 256) row[v] -= lse;
}

// ============================ host ============================
#define SYM(p, s) do { void* _t; cudaGetSymbolAddress(&_t, s); p = (decltype(p))_t; } while (0)

#define SMEM_G128 (128 * 136 * 4)                    /* 69632 >= 2-stage tiles 49152 */
#define SMEM_G32  (2 * (32 + 128) * 48 * 2)          /* 30720 >= epilogue 17408 */

static inline void g128(const __nv_bfloat16* Ah, const __nv_bfloat16* Al, int lda,
                        const __nv_bfloat16* Bh, const __nv_bfloat16* Bl, int ldb,
                        const float* bias, const float* Dadd, int ldd,
                        float* C, int ldc, int M, int N, int KP, int act)
{
    dim3 g((M + 127) / 128, (N + 127) / 128);
    k_wgemm<128><<<g, 256, SMEM_G128>>>(Ah, Al, lda, Bh, Bl, ldb, bias, Dadd, ldd, C, ldc, M, N, KP, act);
}
static inline void g32(const __nv_bfloat16* Ah, const __nv_bfloat16* Al, int lda,
                       const __nv_bfloat16* Bh, const __nv_bfloat16* Bl, int ldb,
                       const float* bias, const float* Dadd, int ldd,
                       float* C, int ldc, int M, int N, int KP, int act)
{
    dim3 g((M + 31) / 32, (N + 127) / 128);
    k_wgemm<32><<<g, 256, SMEM_G32>>>(Ah, Al, lda, Bh, Bl, ldb, bias, Dadd, ldd, C, ldc, M, N, KP, act);
}

extern "C" void kernel_launch(void* const* d_in, const int* in_sizes, int n_in,
                              void* d_out, int out_size)
{
    (void)in_sizes; (void)n_in; (void)out_size;
    const int*   tok  = (const int*)  d_in[0];
    const float* ann  = (const float*)d_in[1];
    const float* emb  = (const float*)d_in[2];
    const float* W_h  = (const float*)d_in[3];
    const float* b_h  = (const float*)d_in[4];
    const float* W_c  = (const float*)d_in[5];
    const float* b_c  = (const float*)d_in[6];
    const float* w_a  = (const float*)d_in[7];
    const float* W_ih = (const float*)d_in[8];
    const float* W_hh = (const float*)d_in[9];
    const float* b_ih = (const float*)d_in[10];
    const float* b_hh = (const float*)d_in[11];
    const float* W_p  = (const float*)d_in[12];
    const float* b_p  = (const float*)d_in[13];

    float* out    = (float*)d_out;
    float* preds  = out;
    float* hidden = out + (size_t)TRGN * BSZ * VOCAB;
    float* attns  = hidden + BSZ * DCH;

    static bool attrDone = false;
    if (!attrDone) {
        cudaFuncSetAttribute(k_wgemm<128>, cudaFuncAttributeMaxDynamicSharedMemorySize, SMEM_G128);
        cudaFuncSetAttribute(k_wgemm<32>,  cudaFuncAttributeMaxDynamicSharedMemorySize, SMEM_G32);
        attrDone = true;
    }

    __nv_bfloat16 *WpH,*WpL,*C2H,*C2L,*annSH,*annSL,*WhcH,*WhcL,*Wc2H,*Wc2L;
    __nv_bfloat16 *Wih1H,*Wih1L,*Wih2H,*Wih2L,*WhH,*WhL,*EmbH,*EmbL;
    __nv_bfloat16 *a0H,*a0L,*hsH,*hsL;
    float *annProj,*annIh,*hbase,*ghp,*giEmb,*bcomb;
    SYM(WpH, d_WpH);   SYM(WpL, d_WpL);
    SYM(C2H, d_C2H);   SYM(C2L, d_C2L);
    SYM(annSH, d_annSH); SYM(annSL, d_annSL);
    SYM(WhcH, d_WhcH); SYM(WhcL, d_WhcL);
    SYM(Wc2H, d_Wc2H); SYM(Wc2L, d_Wc2L);
    SYM(Wih1H, d_Wih1H); SYM(Wih1L, d_Wih1L);
    SYM(Wih2H, d_Wih2H); SYM(Wih2L, d_Wih2L);
    SYM(WhH, d_WhH);   SYM(WhL, d_WhL);
    SYM(EmbH, d_EmbH); SYM(EmbL, d_EmbL);
    SYM(a0H, d_a0H);   SYM(a0L, d_a0L);
    SYM(hsH, d_hsH);   SYM(hsL, d_hsL);
    SYM(annProj, d_annProj); SYM(annIh, d_annIh);
    SYM(hbase, d_hbuf);
    SYM(ghp, d_ghp); SYM(giEmb, d_giEmb);
    SYM(bcomb, d_bcomb);

    const int C2W = EMBED + DCH + 2 * ECH;   // 3620
    const int WIHW = EMBED + 2 * ECH;        // 2620

    // ---- conversions ----
    auto split = [](const float* s, int sld, int off, int rows, int cols,
                    __nv_bfloat16* hi, __nv_bfloat16* lo, int dld) {
        long long tot = (long long)rows * dld;
        k_split<<<(unsigned)((tot + 255) / 256), 256>>>(s, sld, off, rows, cols, hi, lo, dld);
    };
    split(W_p, C2W, 0, VOCAB, C2W, WpH, WpL, KP_WP);
    split(W_hh, DCH, 0, 3 * DCH, DCH, WhcH, WhcL, KP_H);
    split(W_c, DCH + 2 * ECH, 0, DCH, DCH, WhcH + (size_t)3*DCH*KP_H,
          WhcL + (size_t)3*DCH*KP_H, KP_H);                                    // rows 3000..3999 = W_c1
    split(W_c, DCH + 2 * ECH, DCH, DCH, 2 * ECH, Wc2H, Wc2L, KP_CTX);
    split(W_ih, WIHW, 0,     3 * DCH, EMBED,   Wih1H, Wih1L, KP_EMB);
    split(W_ih, WIHW, EMBED, 3 * DCH, 2 * ECH, Wih2H, Wih2L, KP_CTX);
    split(W_h, ECH, 0, DCH, ECH, WhH, WhL, KP_H);
    split(ann, 2 * ECH, 0,   SRC * BSZ, 2 * ECH, annSH, annSL, KP_CTX);
    split(ann, 2 * ECH, ECH, BSZ, ECH, a0H, a0L, KP_H);
    k_bcomb<<<(NGH + 255) / 256, 256>>>(b_hh);
    k_zero<<<(BSZ * VOCAB + 255) / 256, 256>>>(preds, attns, BSZ * VOCAB);
    k_embedS<<<(MROWS * KP_EMB + 255) / 256, 256>>>(tok, emb);

    // ---- h0 = tanh(ann0_bw @ W_h^T + b_h) ----
    g32(a0H, a0L, KP_H, WhH, WhL, KP_H, b_h, nullptr, 0, hbase, DCH, BSZ, DCH, KP_H, 1);
    k_split<<<(BSZ * KP_H + 255) / 256, 256>>>(hbase, DCH, 0, BSZ, DCH, hsH, hsL, KP_H);

    // ---- annProj = ann @ W_c2^T + b_c ----
    g128(annSH, annSL, KP_CTX, Wc2H, Wc2L, KP_CTX, b_c, nullptr, 0,
         annProj, DCH, SRC * BSZ, DCH, KP_CTX, 0);
    // ---- giEmb = embedded @ W_ih1^T + b_ih ----
    g128(EmbH, EmbL, KP_EMB, Wih1H, Wih1L, KP_EMB, b_ih, nullptr, 0,
         giEmb, 3 * DCH, MROWS, 3 * DCH, KP_EMB, 0);
    // ---- annIh = ann @ W_ih2^T (no bias; b_ih lives in giEmb) ----
    g128(annSH, annSL, KP_CTX, Wih2H, Wih2L, KP_CTX, nullptr, nullptr, 0,
         annIh, 3 * DCH, SRC * BSZ, 3 * DCH, KP_CTX, 0);

    // ---- 49-step recurrence: 3 launches per step ----
    for (int i = 0; i < NSTEP; i++) {
        const __nv_bfloat16* hH = hsH + (i & 1) * (BSZ * KP_H);
        const __nv_bfloat16* hL = hsL + (i & 1) * (BSZ * KP_H);
        // [gh | hProj] = h @ [W_hh; W_c1]^T + [b_hh; 0]
        g32(hH, hL, KP_H, WhcH, WhcL, KP_H, bcomb, nullptr, 0,
            ghp, NGH, BSZ, NGH, KP_H, 0);
        k_attn<<<SRC, 256>>>(w_a, attns + (size_t)(i + 1) * SRC * BSZ);
        k_fuse<<<BSZ, 256>>>(ann, i, (i == NSTEP - 1) ? hidden : nullptr);
    }

    // ---- big prediction GEMM straight into preds rows 1..49 ----
    g128(C2H, C2L, KP_WP, WpH, WpL, KP_WP, b_p, nullptr, 0,
         preds + (size_t)BSZ * VOCAB, VOCAB, MROWS, VOCAB, KP_WP, 0);
    k_lsm<<<MROWS, 256>>>(preds + (size_t)BSZ * VOCAB);
}

// round 5
// speedup vs baseline: 5.1358x; 1.0128x over previous
#include <cuda_runtime.h>
#include <cuda_bf16.h>
#include <mma.h>
#include <math.h>
#include <stdint.h>

using namespace nvcuda;

#define SRC 50
#define TRGN 50
#define BSZ 32
#define EMBED 620
#define ECH 1000
#define DCH 1000
#define VOCAB 30000
#define NSTEP 49
#define MROWS (NSTEP*BSZ)          /* 1568 */
#define KP_WP 3648
#define KP_CTX 2048
#define KP_H 1024
#define KP_EMB 640
#define NGH 4000
#define RGRID 128
#define LROWS 1664
#define LCOLS 30208

// ============================ static scratch (bss, zero-initialized) ============================
__device__ __nv_bfloat16 d_WpH[(size_t)VOCAB*KP_WP], d_WpL[(size_t)VOCAB*KP_WP];
__device__ __nv_bfloat16 d_C2H[(size_t)MROWS*KP_WP], d_C2L[(size_t)MROWS*KP_WP];
__device__ __nv_bfloat16 d_annSH[(size_t)SRC*BSZ*KP_CTX], d_annSL[(size_t)SRC*BSZ*KP_CTX];
__device__ __nv_bfloat16 d_WhcH[(size_t)NGH*KP_H], d_WhcL[(size_t)NGH*KP_H];
__device__ __nv_bfloat16 d_Wc2H[(size_t)DCH*KP_CTX], d_Wc2L[(size_t)DCH*KP_CTX];
__device__ __nv_bfloat16 d_Wih1H[(size_t)3*DCH*KP_EMB], d_Wih1L[(size_t)3*DCH*KP_EMB];
__device__ __nv_bfloat16 d_Wih2H[(size_t)3*DCH*KP_CTX], d_Wih2L[(size_t)3*DCH*KP_CTX];
__device__ __nv_bfloat16 d_WhH[DCH*KP_H], d_WhL[DCH*KP_H];
__device__ __nv_bfloat16 d_EmbH[(size_t)MROWS*KP_EMB], d_EmbL[(size_t)MROWS*KP_EMB];
__device__ __nv_bfloat16 d_a0H[BSZ*KP_H], d_a0L[BSZ*KP_H];
__device__ __nv_bfloat16 d_hsH[2][BSZ*KP_H], d_hsL[2][BSZ*KP_H];
__device__ float d_annProj[SRC*BSZ*DCH];
__device__ float d_annIh[(size_t)SRC*BSZ*3*DCH];
__device__ float d_hbuf[2][BSZ*DCH];
__device__ float d_ghp[BSZ*NGH];
__device__ float d_attnS[SRC*BSZ];
__device__ float d_giEmb[(size_t)MROWS*3*DCH];
__device__ float d_bcomb[NGH];
__device__ float d_logits[(size_t)LROWS*LCOLS];

__device__ int g_cnt;
__device__ volatile int g_gen;

// ============================ helpers ============================
__device__ __forceinline__ uint32_t smem_u32(const void* p) {
    uint32_t a;
    asm("{ .reg .u64 t; cvta.to.shared.u64 t, %1; cvt.u32.u64 %0, t; }" : "=r"(a) : "l"(p));
    return a;
}
__device__ __forceinline__ void cp_async16(uint32_t dst, const void* src) {
    asm volatile("cp.async.cg.shared.global [%0], [%1], 16;\n" :: "r"(dst), "l"(src));
}
__device__ __forceinline__ void cp_commit() {
    asm volatile("cp.async.commit_group;\n" ::: "memory");
}
__device__ __forceinline__ void gridbar() {
    __syncthreads();
    if (threadIdx.x == 0) {
        __threadfence();
        int gen = g_gen;
        if (atomicAdd(&g_cnt, 1) == RGRID - 1) {
            g_cnt = 0;
            __threadfence();
            g_gen = gen + 1;
        } else {
            while (g_gen == gen) { __nanosleep(64); }
        }
        __threadfence();
    }
    __syncthreads();
}

// ============================ BIG GEMM: 128x256 tile, 3-stage, direct frag store ============================
#define BLDT 48
#define BSTAGE ((128 + 256) * BLDT)
#define SMEM_BIG (3 * BSTAGE * 2)

__global__ __launch_bounds__(256, 1) void k_wgemmBig()
{
    extern __shared__ __nv_bfloat16 tiles[];
    const int tid = threadIdx.x, wid = tid >> 5;
    const int m0 = blockIdx.x * 128, n0 = blockIdx.y * 256;
    const int wm = wid & 1, wn = wid >> 1;
    const int wmo = wm * 64, wno = wn * 64;

    wmma::fragment<wmma::accumulator, 16, 16, 16, float> acc[4][4];
#pragma unroll
    for (int i = 0; i < 4; i++)
#pragma unroll
        for (int j = 0; j < 4; j++) wmma::fill_fragment(acc[i][j], 0.0f);

    const int cpp = KP_WP >> 5;
    const int total = 3 * cpp;

    auto prefetch = [&](int c, int stage) {
        int p = c / cpp;
        int kc = (c - p * cpp) << 5;
        const __nv_bfloat16* Ap = (p < 2) ? d_C2H : d_C2L;
        const __nv_bfloat16* Bp = (p == 1) ? d_WpL : d_WpH;
        __nv_bfloat16* As = tiles + stage * BSTAGE;
        __nv_bfloat16* Bs = As + 128 * BLDT;
#pragma unroll
        for (int q = 0; q < 2; q++) {
            int it = tid + q * 256;
            int r = it >> 2, seg = it & 3;
            int gm = m0 + r; if (gm >= MROWS) gm = MROWS - 1;
            cp_async16(smem_u32(As + r * BLDT + seg * 8), Ap + (size_t)gm * KP_WP + kc + seg * 8);
        }
#pragma unroll
        for (int q = 0; q < 4; q++) {
            int it = tid + q * 256;
            int r = it >> 2, seg = it & 3;
            int gn = n0 + r; if (gn >= VOCAB) gn = VOCAB - 1;
            cp_async16(smem_u32(Bs + r * BLDT + seg * 8), Bp + (size_t)gn * KP_WP + kc + seg * 8);
        }
        cp_commit();
    };

    prefetch(0, 0);
    prefetch(1, 1);

    for (int c = 0; c < total; c++) {
        if (c + 1 < total) { asm volatile("cp.async.wait_group 1;\n" ::: "memory"); }
        else               { asm volatile("cp.async.wait_group 0;\n" ::: "memory"); }
        __syncthreads();
        if (c + 2 < total) prefetch(c + 2, (c + 2) % 3);
        const __nv_bfloat16* As = tiles + (c % 3) * BSTAGE;
        const __nv_bfloat16* Bs = As + 128 * BLDT;
#pragma unroll
        for (int kk = 0; kk < 32; kk += 16) {
            wmma::fragment<wmma::matrix_a, 16,16,16, __nv_bfloat16, wmma::row_major> af[4];
            wmma::fragment<wmma::matrix_b, 16,16,16, __nv_bfloat16, wmma::col_major> bf[4];
#pragma unroll
            for (int i = 0; i < 4; i++)
                wmma::load_matrix_sync(af[i], As + (wmo + i * 16) * BLDT + kk, BLDT);
#pragma unroll
            for (int j = 0; j < 4; j++)
                wmma::load_matrix_sync(bf[j], Bs + (wno + j * 16) * BLDT + kk, BLDT);
#pragma unroll
            for (int i = 0; i < 4; i++)
#pragma unroll
                for (int j = 0; j < 4; j++)
                    wmma::mma_sync(acc[i][j], af[i], bf[j], acc[i][j]);
        }
        __syncthreads();
    }

#pragma unroll
    for (int i = 0; i < 4; i++)
#pragma unroll
        for (int j = 0; j < 4; j++)
            wmma::store_matrix_sync(d_logits + (size_t)(m0 + wmo + i * 16) * LCOLS + n0 + wno + j * 16,
                                    acc[i][j], LCOLS, wmma::mem_row_major);
}

// ============================ generic WMMA split GEMM (2-stage) ============================
template<int BM>
__global__ __launch_bounds__(256) void k_wgemm(
    const __nv_bfloat16* __restrict__ Ah, const __nv_bfloat16* __restrict__ Al, int lda,
    const __nv_bfloat16* __restrict__ Bh, const __nv_bfloat16* __restrict__ Bl, int ldb,
    const float* __restrict__ bias,
    const float* __restrict__ Dadd, int ldd,
    float* __restrict__ C, int ldc,
    int M, int N, int KP, int act)
{
    constexpr int MFR = (BM == 128) ? 2 : 1;
    constexpr int NFR = (BM == 128) ? 4 : 2;
    constexpr int AITEMS = BM * 4;
    constexpr int LDT = 48;
    constexpr int LDC_S = 136;
    constexpr int STAGE = (BM + 128) * LDT;

    extern __shared__ char smem[];
    __nv_bfloat16* tiles = (__nv_bfloat16*)smem;
    float* Cs = (float*)smem;

    const int tid = threadIdx.x, wid = tid >> 5;
    const int m0 = blockIdx.x * BM, n0 = blockIdx.y * 128;

    int wm, wn;
    if (BM == 128) { wm = wid & 3; wn = wid >> 2; }
    else           { wm = wid & 1; wn = wid >> 1; }
    const int wrow = wm * (16 * MFR);
    const int wcol = wn * (16 * NFR);

    wmma::fragment<wmma::accumulator, 16, 16, 16, float> acc[MFR][NFR];
#pragma unroll
    for (int i = 0; i < MFR; i++)
#pragma unroll
        for (int j = 0; j < NFR; j++)
            wmma::fill_fragment(acc[i][j], 0.0f);

    const int cpp = KP >> 5;
    const int total = 3 * cpp;

    auto prefetch = [&](int c, int stage) {
        int p = c / cpp;
        int kc = (c - p * cpp) << 5;
        const __nv_bfloat16* Ap = (p < 2) ? Ah : Al;
        const __nv_bfloat16* Bp = (p == 1) ? Bl : Bh;
        __nv_bfloat16* As = tiles + stage * STAGE;
        __nv_bfloat16* Bs = As + BM * LDT;
#pragma unroll
        for (int q = 0; q < (BM == 128 ? 2 : 1); q++) {
            int it = tid + q * 256;
            if (BM == 32 && it >= AITEMS) break;
            int r = it >> 2, seg = it & 3;
            int gm = m0 + r; if (gm >= M) gm = M - 1;
            cp_async16(smem_u32(As + r * LDT + seg * 8), Ap + (size_t)gm * lda + kc + seg * 8);
        }
#pragma unroll
        for (int q = 0; q < 2; q++) {
            int it = tid + q * 256;
            int r = it >> 2, seg = it & 3;
            int gn = n0 + r; if (gn >= N) gn = N - 1;
            cp_async16(smem_u32(Bs + r * LDT + seg * 8), Bp + (size_t)gn * ldb + kc + seg * 8);
        }
        cp_commit();
    };

    prefetch(0, 0);
    prefetch(1, 1);

    for (int c = 0; c < total; c++) {
        if (c + 1 < total) { asm volatile("cp.async.wait_group 1;\n" ::: "memory"); }
        else               { asm volatile("cp.async.wait_group 0;\n" ::: "memory"); }
        __syncthreads();
        const __nv_bfloat16* As = tiles + (c & 1) * STAGE;
        const __nv_bfloat16* Bs = As + BM * LDT;
#pragma unroll
        for (int kk = 0; kk < 32; kk += 16) {
            wmma::fragment<wmma::matrix_a, 16,16,16, __nv_bfloat16, wmma::row_major> af[MFR];
            wmma::fragment<wmma::matrix_b, 16,16,16, __nv_bfloat16, wmma::col_major> bf[NFR];
#pragma unroll
            for (int i = 0; i < MFR; i++)
                wmma::load_matrix_sync(af[i], As + (wrow + i * 16) * LDT + kk, LDT);
#pragma unroll
            for (int j = 0; j < NFR; j++)
                wmma::load_matrix_sync(bf[j], Bs + (wcol + j * 16) * LDT + kk, LDT);
#pragma unroll
            for (int i = 0; i < MFR; i++)
#pragma unroll
                for (int j = 0; j < NFR; j++)
                    wmma::mma_sync(acc[i][j], af[i], bf[j], acc[i][j]);
        }
        __syncthreads();
        if (c + 2 < total) prefetch(c + 2, c & 1);
    }

#pragma unroll
    for (int i = 0; i < MFR; i++)
#pragma unroll
        for (int j = 0; j < NFR; j++)
            wmma::store_matrix_sync(Cs + (wrow + i * 16) * LDC_S + wcol + j * 16,
                                    acc[i][j], LDC_S, wmma::mem_row_major);
    __syncthreads();
    for (int idx = tid; idx < BM * 128; idx += 256) {
        int r = idx >> 7, cc = idx & 127;
        int gm = m0 + r, gn = n0 + cc;
        if (gm < M && gn < N) {
            float v = Cs[r * LDC_S + cc];
            if (bias) v += bias[gn];
            if (Dadd) v += Dadd[(size_t)gm * ldd + gn];
            if (act)  v = tanhf(v);
            C[(size_t)gm * ldc + gn] = v;
        }
    }
}

// ============================ persistent recurrence kernel ============================
__global__ __launch_bounds__(256) void k_recur(const float* __restrict__ ann,
                                               const float* __restrict__ w_a,
                                               float* __restrict__ attns,
                                               float* __restrict__ hidden)
{
    __shared__ char smr[40192];
    const int bid = blockIdx.x;
    const int tid = threadIdx.x;
    const int wid = tid >> 5;

    __nv_bfloat16* Ath = (__nv_bfloat16*)smr;
    __nv_bfloat16* Atl = Ath + 2 * 32 * 40;
    __nv_bfloat16* Bth = Atl + 2 * 32 * 40;
    __nv_bfloat16* Btl = Bth + 2 * 64 * 40;
    float* Cs = (float*)(Btl + 2 * 64 * 40);
    float* sc  = (float*)smr;
    float* sat = (float*)smr;
    float* sgi = sat + 64;

    for (int step = 0; step < NSTEP; step++) {
        const int cur = step & 1;
        // ---- phase A: ghp = h @ [W_hh; W_c1]^T + bcomb ----
        if (bid < 63) {
            const int n0 = bid * 64;
            const int wm = wid & 1, wn = wid >> 1;
            const __nv_bfloat16* hH = d_hsH[cur];
            const __nv_bfloat16* hL = d_hsL[cur];
            wmma::fragment<wmma::accumulator, 16, 16, 16, float> acc;
            wmma::fill_fragment(acc, 0.0f);
#pragma unroll 1
            for (int c = 0; c < 32; c++) {
                const int st = c & 1;
                const int kc = c << 5;
                {
                    int it = tid & 127;
                    int r = it >> 2, seg = it & 3;
                    const __nv_bfloat16* src = (tid < 128) ? hH : hL;
                    __nv_bfloat16* dst = ((tid < 128) ? Ath : Atl) + st * (32 * 40);
                    *(uint4*)(dst + r * 40 + seg * 8) =
                        *(const uint4*)(src + (size_t)r * KP_H + kc + seg * 8);
                }
#pragma unroll
                for (int q = 0; q < 2; q++) {
                    int it = tid + q * 256;
                    int r = (it & 255) >> 2, seg = it & 3;
                    int gn = n0 + r; if (gn >= NGH) gn = NGH - 1;
                    const __nv_bfloat16* src = (it < 256) ? d_WhcH : d_WhcL;
                    __nv_bfloat16* dst = ((it < 256) ? Bth : Btl) + st * (64 * 40);
                    *(uint4*)(dst + r * 40 + seg * 8) =
                        *(const uint4*)(src + (size_t)gn * KP_H + kc + seg * 8);
                }
                __syncthreads();
#pragma unroll
                for (int kk = 0; kk < 32; kk += 16) {
                    wmma::fragment<wmma::matrix_a, 16,16,16, __nv_bfloat16, wmma::row_major> ah, al;
                    wmma::fragment<wmma::matrix_b, 16,16,16, __nv_bfloat16, wmma::col_major> bh, bl;
                    wmma::load_matrix_sync(ah, Ath + st * (32*40) + (wm * 16) * 40 + kk, 40);
                    wmma::load_matrix_sync(al, Atl + st * (32*40) + (wm * 16) * 40 + kk, 40);
                    wmma::load_matrix_sync(bh, Bth + st * (64*40) + (wn * 16) * 40 + kk, 40);
                    wmma::load_matrix_sync(bl, Btl + st * (64*40) + (wn * 16) * 40 + kk, 40);
                    wmma::mma_sync(acc, ah, bh, acc);
                    wmma::mma_sync(acc, ah, bl, acc);
                    wmma::mma_sync(acc, al, bh, acc);
                }
            }
            __syncthreads();
            wmma::store_matrix_sync(Cs + (wm * 16) * 72 + wn * 16, acc, 72, wmma::mem_row_major);
            __syncthreads();
            for (int idx = tid; idx < 32 * 64; idx += 256) {
                int r = idx >> 6, cc = idx & 63;
                int gn = n0 + cc;
                if (gn < NGH)
                    d_ghp[r * NGH + gn] = Cs[r * 72 + cc] + d_bcomb[gn];
            }
        }
        gridbar();

        // ---- phase B: attention + softmax over batch ----
        if (bid < SRC) {
            const int s = bid;
            int b = tid >> 3, jt = tid & 7;
            const float* hp = d_ghp + b * NGH + 3 * DCH;
            const float* ap = d_annProj + (size_t)(s * BSZ + b) * DCH;
            float acc = 0.f;
            for (int j = jt; j < DCH; j += 8)
                acc += tanhf(hp[j] + ap[j]) * w_a[j];
            for (int off = 4; off; off >>= 1)
                acc += __shfl_down_sync(0xffffffffu, acc, off, 8);
            if (jt == 0) sc[b] = acc;
            __syncthreads();
            if (tid < 32) {
                float v = sc[tid];
                float m = v;
                for (int off = 16; off; off >>= 1) m = fmaxf(m, __shfl_xor_sync(0xffffffffu, m, off));
                float e = expf(v - m);
                float ssum = e;
                for (int off = 16; off; off >>= 1) ssum += __shfl_xor_sync(0xffffffffu, ssum, off);
                float a = e / ssum;
                d_attnS[s * BSZ + tid] = a;
                attns[(size_t)(step + 1) * SRC * BSZ + s * BSZ + tid] = a;
            }
        }
        gridbar();

        // ---- phase C: context + gi + GRU gates ----
        if (bid < BSZ) {
            const int b = bid;
            if (tid < SRC) sat[tid] = d_attnS[tid * BSZ + b];
            __syncthreads();
            for (int e = tid; e < 2 * ECH; e += 256) {
                float acc = 0.f;
                const float* ap = ann + (size_t)b * (2 * ECH) + e;
#pragma unroll 10
                for (int s = 0; s < SRC; s++)
                    acc += sat[s] * ap[(size_t)s * BSZ * (2 * ECH)];
                __nv_bfloat16 h = __float2bfloat16(acc);
                size_t o = (size_t)(step * BSZ + b) * KP_WP + EMBED + DCH + e;
                d_C2H[o] = h;
                d_C2L[o] = __float2bfloat16(acc - __bfloat162float(h));
            }
            const float* gE = d_giEmb + ((size_t)step * BSZ + b) * 3 * DCH;
            for (int j = tid; j < 3 * DCH; j += 256) {
                float acc = gE[j];
                const float* ip = d_annIh + (size_t)b * 3 * DCH + j;
#pragma unroll 10
                for (int s = 0; s < SRC; s++)
                    acc += sat[s] * ip[(size_t)s * BSZ * 3 * DCH];
                sgi[j] = acc;
            }
            __syncthreads();
            const float* gh = d_ghp + b * NGH;
            for (int j = tid; j < DCH; j += 256) {
                float r = 1.f / (1.f + expf(-(sgi[j] + gh[j])));
                float z = 1.f / (1.f + expf(-(sgi[DCH + j] + gh[DCH + j])));
                float n = tanhf(sgi[2 * DCH + j] + r * gh[2 * DCH + j]);
                float hp = d_hbuf[cur][b * DCH + j];
                float hn = (1.f - z) * n + z * hp;
                d_hbuf[cur ^ 1][b * DCH + j] = hn;
                __nv_bfloat16 hh = __float2bfloat16(hn);
                d_hsH[cur ^ 1][b * KP_H + j] = hh;
                d_hsL[cur ^ 1][b * KP_H + j] = __float2bfloat16(hn - __bfloat162float(hh));
                __nv_bfloat16 ph = __float2bfloat16(hp);
                size_t o = (size_t)(step * BSZ + b) * KP_WP + EMBED + j;
                d_C2H[o] = ph;
                d_C2L[o] = __float2bfloat16(hp - __bfloat162float(ph));
                if (step == NSTEP - 1) hidden[b * DCH + j] = hn;
            }
        }
        gridbar();
    }
}

// ============================ small kernels ============================
__global__ void k_split(const float* __restrict__ src, int sld, int colOff, int rows, int cols,
                        __nv_bfloat16* __restrict__ hi, __nv_bfloat16* __restrict__ lo, int dld)
{
    int i4 = blockIdx.x * blockDim.x + threadIdx.x;
    int total4 = (rows * dld) >> 2;
    if (i4 >= total4) return;
    int i = i4 << 2;
    int r = i / dld, c = i - r * dld;
    float x[4];
    if (c + 3 < cols) {
        float4 v = *(const float4*)(src + (size_t)r * sld + colOff + c);
        x[0] = v.x; x[1] = v.y; x[2] = v.z; x[3] = v.w;
    } else {
#pragma unroll
        for (int q = 0; q < 4; q++)
            x[q] = (c + q < cols) ? src[(size_t)r * sld + colOff + c + q] : 0.f;
    }
    __nv_bfloat16 h[4], l[4];
#pragma unroll
    for (int q = 0; q < 4; q++) {
        h[q] = __float2bfloat16(x[q]);
        l[q] = __float2bfloat16(x[q] - __bfloat162float(h[q]));
    }
    *(uint2*)(hi + i) = *(uint2*)h;
    *(uint2*)(lo + i) = *(uint2*)l;
}

__global__ void k_zero(float* __restrict__ preds0, float* __restrict__ attns0, int n)
{
    int i = blockIdx.x * blockDim.x + threadIdx.x;
    if (i < n) preds0[i] = 0.f;
    if (i < SRC * BSZ) attns0[i] = 0.f;
}

__global__ void k_bcomb(const float* __restrict__ b_hh)
{
    int i = blockIdx.x * blockDim.x + threadIdx.x;
    if (i < NGH) d_bcomb[i] = (i < 3 * DCH) ? b_hh[i] : 0.f;
}

__global__ void k_embedS(const int* __restrict__ tok, const float* __restrict__ emb)
{
    int i = blockIdx.x * blockDim.x + threadIdx.x;
    if (i >= MROWS * KP_EMB) return;
    int m = i / KP_EMB, e = i - m * KP_EMB;
    float x = (e < EMBED) ? emb[(size_t)tok[m] * EMBED + e] : 0.f;
    __nv_bfloat16 h = __float2bfloat16(x);
    __nv_bfloat16 l = __float2bfloat16(x - __bfloat162float(h));
    d_EmbH[i] = h; d_EmbL[i] = l;
    if (e < EMBED) {
        size_t o = (size_t)m * KP_WP + e;
        d_C2H[o] = h; d_C2L[o] = l;
    }
}

__global__ __launch_bounds__(256) void k_lsm(const float* __restrict__ bias, float* __restrict__ preds)
{
    int m = blockIdx.x;
    const float* row = d_logits + (size_t)m * LCOLS;
    float* outr = preds + (size_t)(m + BSZ) * VOCAB;
    int t = threadIdx.x;
    __shared__ float rm[256], rs[256];
    float mx = -1e30f, sum = 0.f;
    for (int v = t; v < VOCAB; v += 256) {
        float x = row[v] + bias[v];
        if (x > mx) { sum = sum * expf(mx - x) + 1.f; mx = x; }
        else sum += expf(x - mx);
    }
    rm[t] = mx; rs[t] = sum; __syncthreads();
    for (int s2 = 128; s2; s2 >>= 1) {
        if (t < s2) {
            float m1 = rm[t], m2 = rm[t + s2];
            float M = fmaxf(m1, m2);
            rs[t] = rs[t] * expf(m1 - M) + rs[t + s2] * expf(m2 - M);
            rm[t] = M;
        }
        __syncthreads();
    }
    float lse = rm[0] + logf(rs[0]);
    for (int v = t; v < VOCAB; v += 256)
        outr[v] = row[v] + bias[v] - lse;
}

// ============================ host ============================
#define SYM(p, s) do { void* _t; cudaGetSymbolAddress(&_t, s); p = (decltype(p))_t; } while (0)

#define SMEM_G128 (128 * 136 * 4)
#define SMEM_G32  (2 * (32 + 128) * 48 * 2)

static inline void g128(const __nv_bfloat16* Ah, const __nv_bfloat16* Al, int lda,
                        const __nv_bfloat16* Bh, const __nv_bfloat16* Bl, int ldb,
                        const float* bias, const float* Dadd, int ldd,
                        float* C, int ldc, int M, int N, int KP, int act)
{
    dim3 g((M + 127) / 128, (N + 127) / 128);
    k_wgemm<128><<<g, 256, SMEM_G128>>>(Ah, Al, lda, Bh, Bl, ldb, bias, Dadd, ldd, C, ldc, M, N, KP, act);
}
static inline void g32(const __nv_bfloat16* Ah, const __nv_bfloat16* Al, int lda,
                       const __nv_bfloat16* Bh, const __nv_bfloat16* Bl, int ldb,
                       const float* bias, const float* Dadd, int ldd,
                       float* C, int ldc, int M, int N, int KP, int act)
{
    dim3 g((M + 31) / 32, (N + 127) / 128);
    k_wgemm<32><<<g, 256, SMEM_G32>>>(Ah, Al, lda, Bh, Bl, ldb, bias, Dadd, ldd, C, ldc, M, N, KP, act);
}

extern "C" void kernel_launch(void* const* d_in, const int* in_sizes, int n_in,
                              void* d_out, int out_size)
{
    (void)in_sizes; (void)n_in; (void)out_size;
    const int*   tok  = (const int*)  d_in[0];
    const float* ann  = (const float*)d_in[1];
    const float* emb  = (const float*)d_in[2];
    const float* W_h  = (const float*)d_in[3];
    const float* b_h  = (const float*)d_in[4];
    const float* W_c  = (const float*)d_in[5];
    const float* b_c  = (const float*)d_in[6];
    const float* w_a  = (const float*)d_in[7];
    const float* W_ih = (const float*)d_in[8];
    const float* W_hh = (const float*)d_in[9];
    const float* b_ih = (const float*)d_in[10];
    const float* b_hh = (const float*)d_in[11];
    const float* W_p  = (const float*)d_in[12];
    const float* b_p  = (const float*)d_in[13];

    float* out    = (float*)d_out;
    float* preds  = out;
    float* hidden = out + (size_t)TRGN * BSZ * VOCAB;
    float* attns  = hidden + BSZ * DCH;

    static bool attrDone = false;
    if (!attrDone) {
        cudaFuncSetAttribute(k_wgemm<128>, cudaFuncAttributeMaxDynamicSharedMemorySize, SMEM_G128);
        cudaFuncSetAttribute(k_wgemm<32>,  cudaFuncAttributeMaxDynamicSharedMemorySize, SMEM_G32);
        cudaFuncSetAttribute(k_wgemmBig,   cudaFuncAttributeMaxDynamicSharedMemorySize, SMEM_BIG);
        attrDone = true;
    }

    __nv_bfloat16 *WpH,*WpL,*annSH,*annSL,*WhcH,*WhcL,*Wc2H,*Wc2L;
    __nv_bfloat16 *Wih1H,*Wih1L,*Wih2H,*Wih2L,*WhH,*WhL,*EmbH,*EmbL,*a0H,*a0L,*hsH,*hsL;
    float *annProj,*annIh,*hbase,*giEmb;
    SYM(WpH, d_WpH);   SYM(WpL, d_WpL);
    SYM(annSH, d_annSH); SYM(annSL, d_annSL);
    SYM(WhcH, d_WhcH); SYM(WhcL, d_WhcL);
    SYM(Wc2H, d_Wc2H); SYM(Wc2L, d_Wc2L);
    SYM(Wih1H, d_Wih1H); SYM(Wih1L, d_Wih1L);
    SYM(Wih2H, d_Wih2H); SYM(Wih2L, d_Wih2L);
    SYM(WhH, d_WhH);   SYM(WhL, d_WhL);
    SYM(EmbH, d_EmbH); SYM(EmbL, d_EmbL);
    SYM(a0H, d_a0H);   SYM(a0L, d_a0L);
    SYM(hsH, d_hsH);   SYM(hsL, d_hsL);
    SYM(annProj, d_annProj); SYM(annIh, d_annIh);
    SYM(hbase, d_hbuf); SYM(giEmb, d_giEmb);

    const int C2W = EMBED + DCH + 2 * ECH;
    const int WIHW = EMBED + 2 * ECH;

    auto split = [](const float* s, int sld, int off, int rows, int cols,
                    __nv_bfloat16* hi, __nv_bfloat16* lo, int dld) {
        long long tot4 = ((long long)rows * dld) >> 2;
        k_split<<<(unsigned)((tot4 + 255) / 256), 256>>>(s, sld, off, rows, cols, hi, lo, dld);
    };
    split(W_p, C2W, 0, VOCAB, C2W, WpH, WpL, KP_WP);
    split(W_hh, DCH, 0, 3 * DCH, DCH, WhcH, WhcL, KP_H);
    split(W_c, DCH + 2 * ECH, 0, DCH, DCH, WhcH + (size_t)3*DCH*KP_H,
          WhcL + (size_t)3*DCH*KP_H, KP_H);
    split(W_c, DCH + 2 * ECH, DCH, DCH, 2 * ECH, Wc2H, Wc2L, KP_CTX);
    split(W_ih, WIHW, 0,     3 * DCH, EMBED,   Wih1H, Wih1L, KP_EMB);
    split(W_ih, WIHW, EMBED, 3 * DCH, 2 * ECH, Wih2H, Wih2L, KP_CTX);
    split(W_h, ECH, 0, DCH, ECH, WhH, WhL, KP_H);
    split(ann, 2 * ECH, 0,   SRC * BSZ, 2 * ECH, annSH, annSL, KP_CTX);
    split(ann, 2 * ECH, ECH, BSZ, ECH, a0H, a0L, KP_H);
    k_bcomb<<<(NGH + 255) / 256, 256>>>(b_hh);
    k_zero<<<(BSZ * VOCAB + 255) / 256, 256>>>(preds, attns, BSZ * VOCAB);
    k_embedS<<<(MROWS * KP_EMB + 255) / 256, 256>>>(tok, emb);

    // h0 = tanh(ann0_bw @ W_h^T + b_h)
    g32(a0H, a0L, KP_H, WhH, WhL, KP_H, b_h, nullptr, 0, hbase, DCH, BSZ, DCH, KP_H, 1);
    split(hbase, DCH, 0, BSZ, DCH, hsH, hsL, KP_H);

    // annProj = ann @ W_c2^T + b_c
    g128(annSH, annSL, KP_CTX, Wc2H, Wc2L, KP_CTX, b_c, nullptr, 0,
         annProj, DCH, SRC * BSZ, DCH, KP_CTX, 0);
    // giEmb = embedded @ W_ih1^T + b_ih
    g128(EmbH, EmbL, KP_EMB, Wih1H, Wih1L, KP_EMB, b_ih, nullptr, 0,
         giEmb, 3 * DCH, MROWS, 3 * DCH, KP_EMB, 0);
    // annIh = ann @ W_ih2^T
    g128(annSH, annSL, KP_CTX, Wih2H, Wih2L, KP_CTX, nullptr, nullptr, 0,
         annIh, 3 * DCH, SRC * BSZ, 3 * DCH, KP_CTX, 0);

    // persistent 49-step recurrence (single launch)
    k_recur<<<RGRID, 256>>>(ann, w_a, attns, hidden);

    // big prediction GEMM -> padded scratch, then fused bias+log_softmax -> preds
    {
        dim3 g(LROWS / 128, LCOLS / 256);   // 13 x 118
        k_wgemmBig<<<g, 256, SMEM_BIG>>>();
    }
    k_lsm<<<MROWS, 256>>>(b_p, preds);
}

// round 7
// speedup vs baseline: 5.4331x; 1.0579x over previous
#include <cuda_runtime.h>
#include <cuda_bf16.h>
#include <mma.h>
#include <math.h>
#include <stdint.h>

using namespace nvcuda;

#define SRC 50
#define TRGN 50
#define BSZ 32
#define EMBED 620
#define ECH 1000
#define DCH 1000
#define VOCAB 30000
#define NSTEP 49
#define MROWS (NSTEP*BSZ)          /* 1568 */
#define KP_WP 3648
#define KP_CTX 2048
#define KP_H 1024
#define KP_EMB 640
#define NGH 4000
#define RGRID 128
#define LROWS 1664
#define LCOLS 30208

// ============================ static scratch (bss, zero-initialized) ============================
__device__ __nv_bfloat16 d_WpH[(size_t)VOCAB*KP_WP], d_WpL[(size_t)VOCAB*KP_WP];
__device__ __nv_bfloat16 d_C2H[(size_t)MROWS*KP_WP], d_C2L[(size_t)MROWS*KP_WP];
__device__ __nv_bfloat16 d_annSH[(size_t)SRC*BSZ*KP_CTX], d_annSL[(size_t)SRC*BSZ*KP_CTX];
__device__ __nv_bfloat16 d_WhcH[(size_t)NGH*KP_H], d_WhcL[(size_t)NGH*KP_H];
__device__ __nv_bfloat16 d_Wc2H[(size_t)DCH*KP_CTX], d_Wc2L[(size_t)DCH*KP_CTX];
__device__ __nv_bfloat16 d_Wih1H[(size_t)3*DCH*KP_EMB], d_Wih1L[(size_t)3*DCH*KP_EMB];
__device__ __nv_bfloat16 d_Wih2H[(size_t)3*DCH*KP_CTX], d_Wih2L[(size_t)3*DCH*KP_CTX];
__device__ __nv_bfloat16 d_WhH[DCH*KP_H], d_WhL[DCH*KP_H];
__device__ __nv_bfloat16 d_EmbH[(size_t)MROWS*KP_EMB], d_EmbL[(size_t)MROWS*KP_EMB];
__device__ __nv_bfloat16 d_a0H[BSZ*KP_H], d_a0L[BSZ*KP_H];
__device__ __nv_bfloat16 d_hsH[2][BSZ*KP_H], d_hsL[2][BSZ*KP_H];
__device__ float d_annProj[SRC*BSZ*DCH];
__device__ float d_annIh[(size_t)SRC*BSZ*3*DCH];
__device__ float d_hbuf[2][BSZ*DCH];
__device__ float d_ghp[BSZ*NGH];
__device__ float d_attnS[SRC*BSZ];
__device__ float d_giEmb[(size_t)MROWS*3*DCH];
__device__ float d_bcomb[NGH];
__device__ float d_logits[(size_t)LROWS*LCOLS];

__device__ int g_cnt;
__device__ volatile int g_gen;

// ============================ helpers ============================
__device__ __forceinline__ uint32_t smem_u32(const void* p) {
    uint32_t a;
    asm("{ .reg .u64 t; cvta.to.shared.u64 t, %1; cvt.u32.u64 %0, t; }" : "=r"(a) : "l"(p));
    return a;
}
__device__ __forceinline__ void cp_async16(uint32_t dst, const void* src) {
    asm volatile("cp.async.cg.shared.global [%0], [%1], 16;\n" :: "r"(dst), "l"(src));
}
__device__ __forceinline__ void cp_commit() {
    asm volatile("cp.async.commit_group;\n" ::: "memory");
}
__device__ __forceinline__ void gridbar() {
    __syncthreads();
    if (threadIdx.x == 0) {
        __threadfence();
        int gen = g_gen;
        if (atomicAdd(&g_cnt, 1) == RGRID - 1) {
            g_cnt = 0;
            __threadfence();
            g_gen = gen + 1;
        } else {
            while (g_gen == gen) { __nanosleep(64); }
        }
        __threadfence();
    }
    __syncthreads();
}

// ============================ BIG GEMM: 128x256 tile, K-chunk 64, 3-stage, LDT 72 (conflict-free) ============================
#define BLDT 72                       /* 144B row stride: ldmatrix bank = 4r mod 32 -> conflict-free */
#define BSTAGE ((128 + 256) * BLDT)   /* bf16 elems per stage = 27648 */
#define SMEM_BIG (3 * BSTAGE * 2)     /* 165888 B */

__global__ __launch_bounds__(256, 1) void k_wgemmBig()
{
    extern __shared__ __nv_bfloat16 tiles[];
    const int tid = threadIdx.x, wid = tid >> 5;
    const int m0 = blockIdx.x * 128, n0 = blockIdx.y * 256;
    const int wm = wid & 1, wn = wid >> 1;
    const int wmo = wm * 64, wno = wn * 64;

    wmma::fragment<wmma::accumulator, 16, 16, 16, float> acc[4][4];
#pragma unroll
    for (int i = 0; i < 4; i++)
#pragma unroll
        for (int j = 0; j < 4; j++) wmma::fill_fragment(acc[i][j], 0.0f);

    const int cpp = KP_WP >> 6;        // 57 chunks of K=64 per product
    const int total = 3 * cpp;         // 171

    auto prefetch = [&](int c, int stage) {
        int p = c / cpp;
        int kc = (c - p * cpp) << 6;
        const __nv_bfloat16* Ap = (p < 2) ? d_C2H : d_C2L;
        const __nv_bfloat16* Bp = (p == 1) ? d_WpL : d_WpH;
        __nv_bfloat16* As = tiles + stage * BSTAGE;
        __nv_bfloat16* Bs = As + 128 * BLDT;
#pragma unroll
        for (int q = 0; q < 4; q++) {          // A: 128 rows x 8 segs = 1024 uint4
            int it = tid + q * 256;
            int r = it >> 3, s = it & 7;
            int gm = m0 + r; if (gm >= MROWS) gm = MROWS - 1;
            cp_async16(smem_u32(As + r * BLDT + s * 8), Ap + (size_t)gm * KP_WP + kc + s * 8);
        }
#pragma unroll
        for (int q = 0; q < 8; q++) {          // B: 256 rows x 8 segs = 2048 uint4
            int it = tid + q * 256;
            int r = it >> 3, s = it & 7;
            int gn = n0 + r; if (gn >= VOCAB) gn = VOCAB - 1;
            cp_async16(smem_u32(Bs + r * BLDT + s * 8), Bp + (size_t)gn * KP_WP + kc + s * 8);
        }
        cp_commit();
    };

    prefetch(0, 0);
    prefetch(1, 1);

    for (int c = 0; c < total; c++) {
        if (c + 1 < total) { asm volatile("cp.async.wait_group 1;\n" ::: "memory"); }
        else               { asm volatile("cp.async.wait_group 0;\n" ::: "memory"); }
        __syncthreads();
        if (c + 2 < total) prefetch(c + 2, (c + 2) % 3);
        const __nv_bfloat16* As = tiles + (c % 3) * BSTAGE;
        const __nv_bfloat16* Bs = As + 128 * BLDT;
#pragma unroll
        for (int kk = 0; kk < 64; kk += 16) {
            wmma::fragment<wmma::matrix_a, 16,16,16, __nv_bfloat16, wmma::row_major> af[4];
            wmma::fragment<wmma::matrix_b, 16,16,16, __nv_bfloat16, wmma::col_major> bf[4];
#pragma unroll
            for (int i = 0; i < 4; i++)
                wmma::load_matrix_sync(af[i], As + (wmo + i * 16) * BLDT + kk, BLDT);
#pragma unroll
            for (int j = 0; j < 4; j++)
                wmma::load_matrix_sync(bf[j], Bs + (wno + j * 16) * BLDT + kk, BLDT);
#pragma unroll
            for (int i = 0; i < 4; i++)
#pragma unroll
                for (int j = 0; j < 4; j++)
                    wmma::mma_sync(acc[i][j], af[i], bf[j], acc[i][j]);
        }
        __syncthreads();
    }

#pragma unroll
    for (int i = 0; i < 4; i++)
#pragma unroll
        for (int j = 0; j < 4; j++)
            wmma::store_matrix_sync(d_logits + (size_t)(m0 + wmo + i * 16) * LCOLS + n0 + wno + j * 16,
                                    acc[i][j], LCOLS, wmma::mem_row_major);
}

// ============================ generic WMMA split GEMM (2-stage, LDT 40 conflict-free) ============================
template<int BM>
__global__ __launch_bounds__(256) void k_wgemm(
    const __nv_bfloat16* __restrict__ Ah, const __nv_bfloat16* __restrict__ Al, int lda,
    const __nv_bfloat16* __restrict__ Bh, const __nv_bfloat16* __restrict__ Bl, int ldb,
    const float* __restrict__ bias,
    const float* __restrict__ Dadd, int ldd,
    float* __restrict__ C, int ldc,
    int M, int N, int KP, int act)
{
    constexpr int MFR = (BM == 128) ? 2 : 1;
    constexpr int NFR = (BM == 128) ? 4 : 2;
    constexpr int AITEMS = BM * 4;
    constexpr int LDT = 40;            // 80B row stride: bank = 20r mod 32, conflict-free ldmatrix
    constexpr int LDC_S = 136;
    constexpr int STAGE = (BM + 128) * LDT;

    extern __shared__ char smem[];
    __nv_bfloat16* tiles = (__nv_bfloat16*)smem;
    float* Cs = (float*)smem;

    const int tid = threadIdx.x, wid = tid >> 5;
    const int m0 = blockIdx.x * BM, n0 = blockIdx.y * 128;

    int wm, wn;
    if (BM == 128) { wm = wid & 3; wn = wid >> 2; }
    else           { wm = wid & 1; wn = wid >> 1; }
    const int wrow = wm * (16 * MFR);
    const int wcol = wn * (16 * NFR);

    wmma::fragment<wmma::accumulator, 16, 16, 16, float> acc[MFR][NFR];
#pragma unroll
    for (int i = 0; i < MFR; i++)
#pragma unroll
        for (int j = 0; j < NFR; j++)
            wmma::fill_fragment(acc[i][j], 0.0f);

    const int cpp = KP >> 5;
    const int total = 3 * cpp;

    auto prefetch = [&](int c, int stage) {
        int p = c / cpp;
        int kc = (c - p * cpp) << 5;
        const __nv_bfloat16* Ap = (p < 2) ? Ah : Al;
        const __nv_bfloat16* Bp = (p == 1) ? Bl : Bh;
        __nv_bfloat16* As = tiles + stage * STAGE;
        __nv_bfloat16* Bs = As + BM * LDT;
#pragma unroll
        for (int q = 0; q < (BM == 128 ? 2 : 1); q++) {
            int it = tid + q * 256;
            if (BM == 32 && it >= AITEMS) break;
            int r = it >> 2, seg = it & 3;
            int gm = m0 + r; if (gm >= M) gm = M - 1;
            cp_async16(smem_u32(As + r * LDT + seg * 8), Ap + (size_t)gm * lda + kc + seg * 8);
        }
#pragma unroll
        for (int q = 0; q < 2; q++) {
            int it = tid + q * 256;
            int r = it >> 2, seg = it & 3;
            int gn = n0 + r; if (gn >= N) gn = N - 1;
            cp_async16(smem_u32(Bs + r * LDT + seg * 8), Bp + (size_t)gn * ldb + kc + seg * 8);
        }
        cp_commit();
    };

    prefetch(0, 0);
    prefetch(1, 1);

    for (int c = 0; c < total; c++) {
        if (c + 1 < total) { asm volatile("cp.async.wait_group 1;\n" ::: "memory"); }
        else               { asm volatile("cp.async.wait_group 0;\n" ::: "memory"); }
        __syncthreads();
        const __nv_bfloat16* As = tiles + (c & 1) * STAGE;
        const __nv_bfloat16* Bs = As + BM * LDT;
#pragma unroll
        for (int kk = 0; kk < 32; kk += 16) {
            wmma::fragment<wmma::matrix_a, 16,16,16, __nv_bfloat16, wmma::row_major> af[MFR];
            wmma::fragment<wmma::matrix_b, 16,16,16, __nv_bfloat16, wmma::col_major> bf[NFR];
#pragma unroll
            for (int i = 0; i < MFR; i++)
                wmma::load_matrix_sync(af[i], As + (wrow + i * 16) * LDT + kk, LDT);
#pragma unroll
            for (int j = 0; j < NFR; j++)
                wmma::load_matrix_sync(bf[j], Bs + (wcol + j * 16) * LDT + kk, LDT);
#pragma unroll
            for (int i = 0; i < MFR; i++)
#pragma unroll
                for (int j = 0; j < NFR; j++)
                    wmma::mma_sync(acc[i][j], af[i], bf[j], acc[i][j]);
        }
        __syncthreads();
        if (c + 2 < total) prefetch(c + 2, c & 1);
    }

#pragma unroll
    for (int i = 0; i < MFR; i++)
#pragma unroll
        for (int j = 0; j < NFR; j++)
            wmma::store_matrix_sync(Cs + (wrow + i * 16) * LDC_S + wcol + j * 16,
                                    acc[i][j], LDC_S, wmma::mem_row_major);
    __syncthreads();
    for (int idx = tid; idx < BM * 128; idx += 256) {
        int r = idx >> 7, cc = idx & 127;
        int gm = m0 + r, gn = n0 + cc;
        if (gm < M && gn < N) {
            float v = Cs[r * LDC_S + cc];
            if (bias) v += bias[gn];
            if (Dadd) v += Dadd[(size_t)gm * ldd + gn];
            if (act)  v = tanhf(v);
            C[(size_t)gm * ldc + gn] = v;
        }
    }
}

// ============================ persistent recurrence kernel ============================
__global__ __launch_bounds__(256) void k_recur(const float* __restrict__ ann,
                                               const float* __restrict__ w_a,
                                               float* __restrict__ attns,
                                               float* __restrict__ hidden)
{
    __shared__ char smr[40192];
    const int bid = blockIdx.x;
    const int tid = threadIdx.x;
    const int wid = tid >> 5;

    __nv_bfloat16* Ath = (__nv_bfloat16*)smr;
    __nv_bfloat16* Atl = Ath + 2 * 32 * 40;
    __nv_bfloat16* Bth = Atl + 2 * 32 * 40;
    __nv_bfloat16* Btl = Bth + 2 * 64 * 40;
    float* Cs = (float*)(Btl + 2 * 64 * 40);
    float* sc  = (float*)smr;
    float* sat = (float*)smr;
    float* sgi = sat + 64;

    for (int step = 0; step < NSTEP; step++) {
        const int cur = step & 1;
        // ---- phase A: ghp = h @ [W_hh; W_c1]^T + bcomb ----
        if (bid < 63) {
            const int n0 = bid * 64;
            const int wm = wid & 1, wn = wid >> 1;
            const __nv_bfloat16* hH = d_hsH[cur];
            const __nv_bfloat16* hL = d_hsL[cur];
            wmma::fragment<wmma::accumulator, 16, 16, 16, float> acc;
            wmma::fill_fragment(acc, 0.0f);
#pragma unroll 1
            for (int c = 0; c < 32; c++) {
                const int st = c & 1;
                const int kc = c << 5;
                {
                    int it = tid & 127;
                    int r = it >> 2, seg = it & 3;
                    const __nv_bfloat16* src = (tid < 128) ? hH : hL;
                    __nv_bfloat16* dst = ((tid < 128) ? Ath : Atl) + st * (32 * 40);
                    *(uint4*)(dst + r * 40 + seg * 8) =
                        *(const uint4*)(src + (size_t)r * KP_H + kc + seg * 8);
                }
#pragma unroll
                for (int q = 0; q < 2; q++) {
                    int it = tid + q * 256;
                    int r = (it & 255) >> 2, seg = it & 3;
                    int gn = n0 + r; if (gn >= NGH) gn = NGH - 1;
                    const __nv_bfloat16* src = (it < 256) ? d_WhcH : d_WhcL;
                    __nv_bfloat16* dst = ((it < 256) ? Bth : Btl) + st * (64 * 40);
                    *(uint4*)(dst + r * 40 + seg * 8) =
                        *(const uint4*)(src + (size_t)gn * KP_H + kc + seg * 8);
                }
                __syncthreads();
#pragma unroll
                for (int kk = 0; kk < 32; kk += 16) {
                    wmma::fragment<wmma::matrix_a, 16,16,16, __nv_bfloat16, wmma::row_major> ah, al;
                    wmma::fragment<wmma::matrix_b, 16,16,16, __nv_bfloat16, wmma::col_major> bh, bl;
                    wmma::load_matrix_sync(ah, Ath + st * (32*40) + (wm * 16) * 40 + kk, 40);
                    wmma::load_matrix_sync(al, Atl + st * (32*40) + (wm * 16) * 40 + kk, 40);
                    wmma::load_matrix_sync(bh, Bth + st * (64*40) + (wn * 16) * 40 + kk, 40);
                    wmma::load_matrix_sync(bl, Btl + st * (64*40) + (wn * 16) * 40 + kk, 40);
                    wmma::mma_sync(acc, ah, bh, acc);
                    wmma::mma_sync(acc, ah, bl, acc);
                    wmma::mma_sync(acc, al, bh, acc);
                }
            }
            __syncthreads();
            wmma::store_matrix_sync(Cs + (wm * 16) * 72 + wn * 16, acc, 72, wmma::mem_row_major);
            __syncthreads();
            for (int idx = tid; idx < 32 * 64; idx += 256) {
                int r = idx >> 6, cc = idx & 63;
                int gn = n0 + cc;
                if (gn < NGH)
                    d_ghp[r * NGH + gn] = Cs[r * 72 + cc] + d_bcomb[gn];
            }
        }
        gridbar();

        // ---- phase B: attention + softmax over batch ----
        if (bid < SRC) {
            const int s = bid;
            int b = tid >> 3, jt = tid & 7;
            const float* hp = d_ghp + b * NGH + 3 * DCH;
            const float* ap = d_annProj + (size_t)(s * BSZ + b) * DCH;
            float acc = 0.f;
            for (int j = jt; j < DCH; j += 8)
                acc += tanhf(hp[j] + ap[j]) * w_a[j];
            for (int off = 4; off; off >>= 1)
                acc += __shfl_down_sync(0xffffffffu, acc, off, 8);
            if (jt == 0) sc[b] = acc;
            __syncthreads();
            if (tid < 32) {
                float v = sc[tid];
                float m = v;
                for (int off = 16; off; off >>= 1) m = fmaxf(m, __shfl_xor_sync(0xffffffffu, m, off));
                float e = expf(v - m);
                float ssum = e;
                for (int off = 16; off; off >>= 1) ssum += __shfl_xor_sync(0xffffffffu, ssum, off);
                float a = e / ssum;
                d_attnS[s * BSZ + tid] = a;
                attns[(size_t)(step + 1) * SRC * BSZ + s * BSZ + tid] = a;
            }
        }
        gridbar();

        // ---- phase C: context + gi + GRU gates ----
        if (bid < BSZ) {
            const int b = bid;
            if (tid < SRC) sat[tid] = d_attnS[tid * BSZ + b];
            __syncthreads();
            for (int e = tid; e < 2 * ECH; e += 256) {
                float acc = 0.f;
                const float* ap = ann + (size_t)b * (2 * ECH) + e;
#pragma unroll 10
                for (int s = 0; s < SRC; s++)
                    acc += sat[s] * ap[(size_t)s * BSZ * (2 * ECH)];
                __nv_bfloat16 h = __float2bfloat16(acc);
                size_t o = (size_t)(step * BSZ + b) * KP_WP + EMBED + DCH + e;
                d_C2H[o] = h;
                d_C2L[o] = __float2bfloat16(acc - __bfloat162float(h));
            }
            const float* gE = d_giEmb + ((size_t)step * BSZ + b) * 3 * DCH;
            for (int j = tid; j < 3 * DCH; j += 256) {
                float acc = gE[j];
                const float* ip = d_annIh + (size_t)b * 3 * DCH + j;
#pragma unroll 10
                for (int s = 0; s < SRC; s++)
                    acc += sat[s] * ip[(size_t)s * BSZ * 3 * DCH];
                sgi[j] = acc;
            }
            __syncthreads();
            const float* gh = d_ghp + b * NGH;
            for (int j = tid; j < DCH; j += 256) {
                float r = 1.f / (1.f + expf(-(sgi[j] + gh[j])));
                float z = 1.f / (1.f + expf(-(sgi[DCH + j] + gh[DCH + j])));
                float n = tanhf(sgi[2 * DCH + j] + r * gh[2 * DCH + j]);
                float hp = d_hbuf[cur][b * DCH + j];
                float hn = (1.f - z) * n + z * hp;
                d_hbuf[cur ^ 1][b * DCH + j] = hn;
                __nv_bfloat16 hh = __float2bfloat16(hn);
                d_hsH[cur ^ 1][b * KP_H + j] = hh;
                d_hsL[cur ^ 1][b * KP_H + j] = __float2bfloat16(hn - __bfloat162float(hh));
                __nv_bfloat16 ph = __float2bfloat16(hp);
                size_t o = (size_t)(step * BSZ + b) * KP_WP + EMBED + j;
                d_C2H[o] = ph;
                d_C2L[o] = __float2bfloat16(hp - __bfloat162float(ph));
                if (step == NSTEP - 1) hidden[b * DCH + j] = hn;
            }
        }
        gridbar();
    }
}

// ============================ small kernels ============================
__global__ void k_split(const float* __restrict__ src, int sld, int colOff, int rows, int cols,
                        __nv_bfloat16* __restrict__ hi, __nv_bfloat16* __restrict__ lo, int dld)
{
    int i4 = blockIdx.x * blockDim.x + threadIdx.x;
    int total4 = (rows * dld) >> 2;
    if (i4 >= total4) return;
    int i = i4 << 2;
    int r = i / dld, c = i - r * dld;
    float x[4];
    if (c + 3 < cols) {
        float4 v = *(const float4*)(src + (size_t)r * sld + colOff + c);
        x[0] = v.x; x[1] = v.y; x[2] = v.z; x[3] = v.w;
    } else {
#pragma unroll
        for (int q = 0; q < 4; q++)
            x[q] = (c + q < cols) ? src[(size_t)r * sld + colOff + c + q] : 0.f;
    }
    __nv_bfloat16 h[4], l[4];
#pragma unroll
    for (int q = 0; q < 4; q++) {
        h[q] = __float2bfloat16(x[q]);
        l[q] = __float2bfloat16(x[q] - __bfloat162float(h[q]));
    }
    *(uint2*)(hi + i) = *(uint2*)h;
    *(uint2*)(lo + i) = *(uint2*)l;
}

__global__ void k_zero(float* __restrict__ preds0, float* __restrict__ attns0, int n)
{
    int i = blockIdx.x * blockDim.x + threadIdx.x;
    if (i < n) preds0[i] = 0.f;
    if (i < SRC * BSZ) attns0[i] = 0.f;
}

__global__ void k_bcomb(const float* __restrict__ b_hh)
{
    int i = blockIdx.x * blockDim.x + threadIdx.x;
    if (i < NGH) d_bcomb[i] = (i < 3 * DCH) ? b_hh[i] : 0.f;
}

__global__ void k_embedS(const int* __restrict__ tok, const float* __restrict__ emb)
{
    int i = blockIdx.x * blockDim.x + threadIdx.x;
    if (i >= MROWS * KP_EMB) return;
    int m = i / KP_EMB, e = i - m * KP_EMB;
    float x = (e < EMBED) ? emb[(size_t)tok[m] * EMBED + e] : 0.f;
    __nv_bfloat16 h = __float2bfloat16(x);
    __nv_bfloat16 l = __float2bfloat16(x - __bfloat162float(h));
    d_EmbH[i] = h; d_EmbL[i] = l;
    if (e < EMBED) {
        size_t o = (size_t)m * KP_WP + e;
        d_C2H[o] = h; d_C2L[o] = l;
    }
}

__global__ __launch_bounds__(256) void k_lsm(const float* __restrict__ bias, float* __restrict__ preds)
{
    int m = blockIdx.x;
    const float* row = d_logits + (size_t)m * LCOLS;
    float* outr = preds + (size_t)(m + BSZ) * VOCAB;
    int t = threadIdx.x;
    __shared__ float rm[256], rs[256];
    float mx = -1e30f, sum = 0.f;
    for (int v = t; v < VOCAB; v += 256) {
        float x = row[v] + bias[v];
        if (x > mx) { sum = sum * expf(mx - x) + 1.f; mx = x; }
        else sum += expf(x - mx);
    }
    rm[t] = mx; rs[t] = sum; __syncthreads();
    for (int s2 = 128; s2; s2 >>= 1) {
        if (t < s2) {
            float m1 = rm[t], m2 = rm[t + s2];
            float M = fmaxf(m1, m2);
            rs[t] = rs[t] * expf(m1 - M) + rs[t + s2] * expf(m2 - M);
            rm[t] = M;
        }
        __syncthreads();
    }
    float lse = rm[0] + logf(rs[0]);
    for (int v = t; v < VOCAB; v += 256)
        outr[v] = row[v] + bias[v] - lse;
}

// ============================ host ============================
#define SYM(p, s) do { void* _t; cudaGetSymbolAddress(&_t, s); p = (decltype(p))_t; } while (0)

#define SMEM_G128 (128 * 136 * 4)
#define SMEM_G32  (2 * (32 + 128) * 40 * 2 + 1024)

static inline void g128(const __nv_bfloat16* Ah, const __nv_bfloat16* Al, int lda,
                        const __nv_bfloat16* Bh, const __nv_bfloat16* Bl, int ldb,
                        const float* bias, const float* Dadd, int ldd,
                        float* C, int ldc, int M, int N, int KP, int act)
{
    dim3 g((M + 127) / 128, (N + 127) / 128);
    k_wgemm<128><<<g, 256, SMEM_G128>>>(Ah, Al, lda, Bh, Bl, ldb, bias, Dadd, ldd, C, ldc, M, N, KP, act);
}
static inline void g32(const __nv_bfloat16* Ah, const __nv_bfloat16* Al, int lda,
                       const __nv_bfloat16* Bh, const __nv_bfloat16* Bl, int ldb,
                       const float* bias, const float* Dadd, int ldd,
                       float* C, int ldc, int M, int N, int KP, int act)
{
    dim3 g((M + 31) / 32, (N + 127) / 128);
    k_wgemm<32><<<g, 256, SMEM_G32>>>(Ah, Al, lda, Bh, Bl, ldb, bias, Dadd, ldd, C, ldc, M, N, KP, act);
}

extern "C" void kernel_launch(void* const* d_in, const int* in_sizes, int n_in,
                              void* d_out, int out_size)
{
    (void)in_sizes; (void)n_in; (void)out_size;
    const int*   tok  = (const int*)  d_in[0];
    const float* ann  = (const float*)d_in[1];
    const float* emb  = (const float*)d_in[2];
    const float* W_h  = (const float*)d_in[3];
    const float* b_h  = (const float*)d_in[4];
    const float* W_c  = (const float*)d_in[5];
    const float* b_c  = (const float*)d_in[6];
    const float* w_a  = (const float*)d_in[7];
    const float* W_ih = (const float*)d_in[8];
    const float* W_hh = (const float*)d_in[9];
    const float* b_ih = (const float*)d_in[10];
    const float* b_hh = (const float*)d_in[11];
    const float* W_p  = (const float*)d_in[12];
    const float* b_p  = (const float*)d_in[13];

    float* out    = (float*)d_out;
    float* preds  = out;
    float* hidden = out + (size_t)TRGN * BSZ * VOCAB;
    float* attns  = hidden + BSZ * DCH;

    static bool attrDone = false;
    if (!attrDone) {
        cudaFuncSetAttribute(k_wgemm<128>, cudaFuncAttributeMaxDynamicSharedMemorySize, SMEM_G128);
        cudaFuncSetAttribute(k_wgemm<32>,  cudaFuncAttributeMaxDynamicSharedMemorySize, SMEM_G32);
        cudaFuncSetAttribute(k_wgemmBig,   cudaFuncAttributeMaxDynamicSharedMemorySize, SMEM_BIG);
        attrDone = true;
    }

    __nv_bfloat16 *WpH,*WpL,*annSH,*annSL,*WhcH,*WhcL,*Wc2H,*Wc2L;
    __nv_bfloat16 *Wih1H,*Wih1L,*Wih2H,*Wih2L,*WhH,*WhL,*EmbH,*EmbL,*a0H,*a0L,*hsH,*hsL;
    float *annProj,*annIh,*hbase,*giEmb;
    SYM(WpH, d_WpH);   SYM(WpL, d_WpL);
    SYM(annSH, d_annSH); SYM(annSL, d_annSL);
    SYM(WhcH, d_WhcH); SYM(WhcL, d_WhcL);
    SYM(Wc2H, d_Wc2H); SYM(Wc2L, d_Wc2L);
    SYM(Wih1H, d_Wih1H); SYM(Wih1L, d_Wih1L);
    SYM(Wih2H, d_Wih2H); SYM(Wih2L, d_Wih2L);
    SYM(WhH, d_WhH);   SYM(WhL, d_WhL);
    SYM(EmbH, d_EmbH); SYM(EmbL, d_EmbL);
    SYM(a0H, d_a0H);   SYM(a0L, d_a0L);
    SYM(hsH, d_hsH);   SYM(hsL, d_hsL);
    SYM(annProj, d_annProj); SYM(annIh, d_annIh);
    SYM(hbase, d_hbuf); SYM(giEmb, d_giEmb);

    const int C2W = EMBED + DCH + 2 * ECH;
    const int WIHW = EMBED + 2 * ECH;

    auto split = [](const float* s, int sld, int off, int rows, int cols,
                    __nv_bfloat16* hi, __nv_bfloat16* lo, int dld) {
        long long tot4 = ((long long)rows * dld) >> 2;
        k_split<<<(unsigned)((tot4 + 255) / 256), 256>>>(s, sld, off, rows, cols, hi, lo, dld);
    };
    split(W_p, C2W, 0, VOCAB, C2W, WpH, WpL, KP_WP);
    split(W_hh, DCH, 0, 3 * DCH, DCH, WhcH, WhcL, KP_H);
    split(W_c, DCH + 2 * ECH, 0, DCH, DCH, WhcH + (size_t)3*DCH*KP_H,
          WhcL + (size_t)3*DCH*KP_H, KP_H);
    split(W_c, DCH + 2 * ECH, DCH, DCH, 2 * ECH, Wc2H, Wc2L, KP_CTX);
    split(W_ih, WIHW, 0,     3 * DCH, EMBED,   Wih1H, Wih1L, KP_EMB);
    split(W_ih, WIHW, EMBED, 3 * DCH, 2 * ECH, Wih2H, Wih2L, KP_CTX);
    split(W_h, ECH, 0, DCH, ECH, WhH, WhL, KP_H);
    split(ann, 2 * ECH, 0,   SRC * BSZ, 2 * ECH, annSH, annSL, KP_CTX);
    split(ann, 2 * ECH, ECH, BSZ, ECH, a0H, a0L, KP_H);
    k_bcomb<<<(NGH + 255) / 256, 256>>>(b_hh);
    k_zero<<<(BSZ * VOCAB + 255) / 256, 256>>>(preds, attns, BSZ * VOCAB);
    k_embedS<<<(MROWS * KP_EMB + 255) / 256, 256>>>(tok, emb);

    // h0 = tanh(ann0_bw @ W_h^T + b_h)
    g32(a0H, a0L, KP_H, WhH, WhL, KP_H, b_h, nullptr, 0, hbase, DCH, BSZ, DCH, KP_H, 1);
    split(hbase, DCH, 0, BSZ, DCH, hsH, hsL, KP_H);

    // annProj = ann @ W_c2^T + b_c
    g128(annSH, annSL, KP_CTX, Wc2H, Wc2L, KP_CTX, b_c, nullptr, 0,
         annProj, DCH, SRC * BSZ, DCH, KP_CTX, 0);
    // giEmb = embedded @ W_ih1^T + b_ih
    g128(EmbH, EmbL, KP_EMB, Wih1H, Wih1L, KP_EMB, b_ih, nullptr, 0,
         giEmb, 3 * DCH, MROWS, 3 * DCH, KP_EMB, 0);
    // annIh = ann @ W_ih2^T
    g128(annSH, annSL, KP_CTX, Wih2H, Wih2L, KP_CTX, nullptr, nullptr, 0,
         annIh, 3 * DCH, SRC * BSZ, 3 * DCH, KP_CTX, 0);

    // persistent 49-step recurrence (single launch)
    k_recur<<<RGRID, 256>>>(ann, w_a, attns, hidden);

    // big prediction GEMM -> padded scratch, then fused bias+log_softmax -> preds
    {
        dim3 g(LROWS / 128, LCOLS / 256);   // 13 x 118
        k_wgemmBig<<<g, 256, SMEM_BIG>>>();
    }
    k_lsm<<<MROWS, 256>>>(b_p, preds);
}

// round 8
// speedup vs baseline: 7.4376x; 1.3689x over previous
#include <cuda_runtime.h>
#include <cuda_bf16.h>
#include <cuda_fp16.h>
#include <mma.h>
#include <math.h>
#include <stdint.h>

using namespace nvcuda;

#define SRC 50
#define TRGN 50
#define BSZ 32
#define EMBED 620
#define ECH 1000
#define DCH 1000
#define VOCAB 30000
#define NSTEP 49
#define MROWS (NSTEP*BSZ)          /* 1568 */
#define KP_WP 3648
#define KP_CTX 2048
#define KP_H 1024
#define KP_EMB 640
#define NGH 4000
#define RGRID 64
#define LROWS 1664
#define LCOLS 30208

// ============================ static scratch (bss, zero-initialized) ============================
__device__ __half d_Wp16H[(size_t)VOCAB*KP_WP], d_Wp16L[(size_t)VOCAB*KP_WP];  // W_p fp16 hi/lo
__device__ __half d_C2[(size_t)MROWS*KP_WP];                                    // comb2, single fp16
__device__ __nv_bfloat16 d_annSH[(size_t)SRC*BSZ*KP_CTX], d_annSL[(size_t)SRC*BSZ*KP_CTX];
__device__ __nv_bfloat16 d_WhcH[(size_t)NGH*KP_H], d_WhcL[(size_t)NGH*KP_H];
__device__ __nv_bfloat16 d_Wc2H[(size_t)DCH*KP_CTX], d_Wc2L[(size_t)DCH*KP_CTX];
__device__ __nv_bfloat16 d_Wih1H[(size_t)3*DCH*KP_EMB], d_Wih1L[(size_t)3*DCH*KP_EMB];
__device__ __nv_bfloat16 d_Wih2H[(size_t)3*DCH*KP_CTX], d_Wih2L[(size_t)3*DCH*KP_CTX];
__device__ __nv_bfloat16 d_WhH[DCH*KP_H], d_WhL[DCH*KP_H];
__device__ __nv_bfloat16 d_EmbH[(size_t)MROWS*KP_EMB], d_EmbL[(size_t)MROWS*KP_EMB];
__device__ __nv_bfloat16 d_a0H[BSZ*KP_H], d_a0L[BSZ*KP_H];
__device__ __nv_bfloat16 d_hsH[2][BSZ*KP_H], d_hsL[2][BSZ*KP_H];
__device__ float d_annProj[SRC*BSZ*DCH];
__device__ float d_annIh[(size_t)SRC*BSZ*3*DCH];
__device__ float d_hbuf[2][BSZ*DCH];
__device__ float d_ghp[BSZ*NGH];
__device__ float d_attnS[SRC*BSZ];
__device__ float d_giEmb[(size_t)MROWS*3*DCH];
__device__ float d_bcomb[NGH];
__device__ float d_logits[(size_t)LROWS*LCOLS];

__device__ int g_cnt;
__device__ volatile int g_gen;

// ============================ helpers ============================
__device__ __forceinline__ uint32_t smem_u32(const void* p) {
    uint32_t a;
    asm("{ .reg .u64 t; cvta.to.shared.u64 t, %1; cvt.u32.u64 %0, t; }" : "=r"(a) : "l"(p));
    return a;
}
__device__ __forceinline__ void cp_async16(uint32_t dst, const void* src) {
    asm volatile("cp.async.cg.shared.global [%0], [%1], 16;\n" :: "r"(dst), "l"(src));
}
__device__ __forceinline__ void cp_commit() {
    asm volatile("cp.async.commit_group;\n" ::: "memory");
}
__device__ __forceinline__ void gridbar() {
    __syncthreads();
    if (threadIdx.x == 0) {
        __threadfence();
        int gen = g_gen;
        if (atomicAdd(&g_cnt, 1) == RGRID - 1) {
            g_cnt = 0;
            __threadfence();
            g_gen = gen + 1;
        } else {
            while (g_gen == gen) { __nanosleep(64); }
        }
        __threadfence();
    }
    __syncthreads();
}

// ============================ BIG GEMM: fp16 2-product, 128x256 tile, K-chunk 64, 3-stage ============================
// logits = C2 @ (Wp16H + Wp16L)^T  (A rounded once to fp16; B exact fp16 split)
#define BLDT 72
#define BSTAGE ((128 + 256) * BLDT)
#define SMEM_BIG (3 * BSTAGE * 2)

__global__ __launch_bounds__(256, 1) void k_wgemmBig()
{
    extern __shared__ __half tiles[];
    const int tid = threadIdx.x, wid = tid >> 5;
    const int m0 = blockIdx.x * 128, n0 = blockIdx.y * 256;
    const int wm = wid & 1, wn = wid >> 1;
    const int wmo = wm * 64, wno = wn * 64;

    wmma::fragment<wmma::accumulator, 16, 16, 16, float> acc[4][4];
#pragma unroll
    for (int i = 0; i < 4; i++)
#pragma unroll
        for (int j = 0; j < 4; j++) wmma::fill_fragment(acc[i][j], 0.0f);

    const int cpp = KP_WP >> 6;        // 57
    const int total = 2 * cpp;         // 114: products C2*WpH, C2*WpL

    auto prefetch = [&](int c, int stage) {
        int p = c / cpp;
        int kc = (c - p * cpp) << 6;
        const __half* Bp = (p == 0) ? d_Wp16H : d_Wp16L;
        __half* As = tiles + stage * BSTAGE;
        __half* Bs = As + 128 * BLDT;
#pragma unroll
        for (int q = 0; q < 4; q++) {          // A: 128 rows x 8 segs
            int it = tid + q * 256;
            int r = it >> 3, s = it & 7;
            int gm = m0 + r; if (gm >= MROWS) gm = MROWS - 1;
            cp_async16(smem_u32(As + r * BLDT + s * 8), d_C2 + (size_t)gm * KP_WP + kc + s * 8);
        }
#pragma unroll
        for (int q = 0; q < 8; q++) {          // B: 256 rows x 8 segs
            int it = tid + q * 256;
            int r = it >> 3, s = it & 7;
            int gn = n0 + r; if (gn >= VOCAB) gn = VOCAB - 1;
            cp_async16(smem_u32(Bs + r * BLDT + s * 8), Bp + (size_t)gn * KP_WP + kc + s * 8);
        }
        cp_commit();
    };

    prefetch(0, 0);
    prefetch(1, 1);

    for (int c = 0; c < total; c++) {
        if (c + 1 < total) { asm volatile("cp.async.wait_group 1;\n" ::: "memory"); }
        else               { asm volatile("cp.async.wait_group 0;\n" ::: "memory"); }
        __syncthreads();
        if (c + 2 < total) prefetch(c + 2, (c + 2) % 3);
        const __half* As = tiles + (c % 3) * BSTAGE;
        const __half* Bs = As + 128 * BLDT;
#pragma unroll
        for (int kk = 0; kk < 64; kk += 16) {
            wmma::fragment<wmma::matrix_a, 16,16,16, __half, wmma::row_major> af[4];
            wmma::fragment<wmma::matrix_b, 16,16,16, __half, wmma::col_major> bf[4];
#pragma unroll
            for (int i = 0; i < 4; i++)
                wmma::load_matrix_sync(af[i], As + (wmo + i * 16) * BLDT + kk, BLDT);
#pragma unroll
            for (int j = 0; j < 4; j++)
                wmma::load_matrix_sync(bf[j], Bs + (wno + j * 16) * BLDT + kk, BLDT);
#pragma unroll
            for (int i = 0; i < 4; i++)
#pragma unroll
                for (int j = 0; j < 4; j++)
                    wmma::mma_sync(acc[i][j], af[i], bf[j], acc[i][j]);
        }
        __syncthreads();
    }

#pragma unroll
    for (int i = 0; i < 4; i++)
#pragma unroll
        for (int j = 0; j < 4; j++)
            wmma::store_matrix_sync(d_logits + (size_t)(m0 + wmo + i * 16) * LCOLS + n0 + wno + j * 16,
                                    acc[i][j], LCOLS, wmma::mem_row_major);
}

// ============================ generic WMMA bf16 split GEMM (unchanged, 2-stage, LDT 40) ============================
template<int BM>
__global__ __launch_bounds__(256) void k_wgemm(
    const __nv_bfloat16* __restrict__ Ah, const __nv_bfloat16* __restrict__ Al, int lda,
    const __nv_bfloat16* __restrict__ Bh, const __nv_bfloat16* __restrict__ Bl, int ldb,
    const float* __restrict__ bias,
    const float* __restrict__ Dadd, int ldd,
    float* __restrict__ C, int ldc,
    int M, int N, int KP, int act)
{
    constexpr int MFR = (BM == 128) ? 2 : 1;
    constexpr int NFR = (BM == 128) ? 4 : 2;
    constexpr int AITEMS = BM * 4;
    constexpr int LDT = 40;
    constexpr int LDC_S = 136;
    constexpr int STAGE = (BM + 128) * LDT;

    extern __shared__ char smem[];
    __nv_bfloat16* tiles = (__nv_bfloat16*)smem;
    float* Cs = (float*)smem;

    const int tid = threadIdx.x, wid = tid >> 5;
    const int m0 = blockIdx.x * BM, n0 = blockIdx.y * 128;

    int wm, wn;
    if (BM == 128) { wm = wid & 3; wn = wid >> 2; }
    else           { wm = wid & 1; wn = wid >> 1; }
    const int wrow = wm * (16 * MFR);
    const int wcol = wn * (16 * NFR);

    wmma::fragment<wmma::accumulator, 16, 16, 16, float> acc[MFR][NFR];
#pragma unroll
    for (int i = 0; i < MFR; i++)
#pragma unroll
        for (int j = 0; j < NFR; j++)
            wmma::fill_fragment(acc[i][j], 0.0f);

    const int cpp = KP >> 5;
    const int total = 3 * cpp;

    auto prefetch = [&](int c, int stage) {
        int p = c / cpp;
        int kc = (c - p * cpp) << 5;
        const __nv_bfloat16* Ap = (p < 2) ? Ah : Al;
        const __nv_bfloat16* Bp = (p == 1) ? Bl : Bh;
        __nv_bfloat16* As = tiles + stage * STAGE;
        __nv_bfloat16* Bs = As + BM * LDT;
#pragma unroll
        for (int q = 0; q < (BM == 128 ? 2 : 1); q++) {
            int it = tid + q * 256;
            if (BM == 32 && it >= AITEMS) break;
            int r = it >> 2, seg = it & 3;
            int gm = m0 + r; if (gm >= M) gm = M - 1;
            cp_async16(smem_u32(As + r * LDT + seg * 8), Ap + (size_t)gm * lda + kc + seg * 8);
        }
#pragma unroll
        for (int q = 0; q < 2; q++) {
            int it = tid + q * 256;
            int r = it >> 2, seg = it & 3;
            int gn = n0 + r; if (gn >= N) gn = N - 1;
            cp_async16(smem_u32(Bs + r * LDT + seg * 8), Bp + (size_t)gn * ldb + kc + seg * 8);
        }
        cp_commit();
    };

    prefetch(0, 0);
    prefetch(1, 1);

    for (int c = 0; c < total; c++) {
        if (c + 1 < total) { asm volatile("cp.async.wait_group 1;\n" ::: "memory"); }
        else               { asm volatile("cp.async.wait_group 0;\n" ::: "memory"); }
        __syncthreads();
        const __nv_bfloat16* As = tiles + (c & 1) * STAGE;
        const __nv_bfloat16* Bs = As + BM * LDT;
#pragma unroll
        for (int kk = 0; kk < 32; kk += 16) {
            wmma::fragment<wmma::matrix_a, 16,16,16, __nv_bfloat16, wmma::row_major> af[MFR];
            wmma::fragment<wmma::matrix_b, 16,16,16, __nv_bfloat16, wmma::col_major> bf[NFR];
#pragma unroll
            for (int i = 0; i < MFR; i++)
                wmma::load_matrix_sync(af[i], As + (wrow + i * 16) * LDT + kk, LDT);
#pragma unroll
            for (int j = 0; j < NFR; j++)
                wmma::load_matrix_sync(bf[j], Bs + (wcol + j * 16) * LDT + kk, LDT);
#pragma unroll
            for (int i = 0; i < MFR; i++)
#pragma unroll
                for (int j = 0; j < NFR; j++)
                    wmma::mma_sync(acc[i][j], af[i], bf[j], acc[i][j]);
        }
        __syncthreads();
        if (c + 2 < total) prefetch(c + 2, c & 1);
    }

#pragma unroll
    for (int i = 0; i < MFR; i++)
#pragma unroll
        for (int j = 0; j < NFR; j++)
            wmma::store_matrix_sync(Cs + (wrow + i * 16) * LDC_S + wcol + j * 16,
                                    acc[i][j], LDC_S, wmma::mem_row_major);
    __syncthreads();
    for (int idx = tid; idx < BM * 128; idx += 256) {
        int r = idx >> 7, cc = idx & 127;
        int gm = m0 + r, gn = n0 + cc;
        if (gm < M && gn < N) {
            float v = Cs[r * LDC_S + cc];
            if (bias) v += bias[gn];
            if (Dadd) v += Dadd[(size_t)gm * ldd + gn];
            if (act)  v = tanhf(v);
            C[(size_t)gm * ldc + gn] = v;
        }
    }
}

// ============================ persistent recurrence kernel ============================
__global__ __launch_bounds__(256) void k_recur(const float* __restrict__ ann,
                                               const float* __restrict__ w_a,
                                               float* __restrict__ attns,
                                               float* __restrict__ hidden)
{
    __shared__ char smr[40192];
    const int bid = blockIdx.x;
    const int tid = threadIdx.x;
    const int wid = tid >> 5;

    __nv_bfloat16* Ath = (__nv_bfloat16*)smr;
    __nv_bfloat16* Atl = Ath + 2 * 32 * 40;
    __nv_bfloat16* Bth = Atl + 2 * 32 * 40;
    __nv_bfloat16* Btl = Bth + 2 * 64 * 40;
    float* Cs = (float*)(Btl + 2 * 64 * 40);
    float* sc  = (float*)smr;
    float* sat = (float*)smr;
    float* sgi = sat + 64;

    for (int step = 0; step < NSTEP; step++) {
        const int cur = step & 1;
        // ---- phase A: ghp = h @ [W_hh; W_c1]^T + bcomb ----
        if (bid < 63) {
            const int n0 = bid * 64;
            const int wm = wid & 1, wn = wid >> 1;
            const __nv_bfloat16* hH = d_hsH[cur];
            const __nv_bfloat16* hL = d_hsL[cur];
            wmma::fragment<wmma::accumulator, 16, 16, 16, float> acc;
            wmma::fill_fragment(acc, 0.0f);
#pragma unroll 1
            for (int c = 0; c < 32; c++) {
                const int st = c & 1;
                const int kc = c << 5;
                {
                    int it = tid & 127;
                    int r = it >> 2, seg = it & 3;
                    const __nv_bfloat16* src = (tid < 128) ? hH : hL;
                    __nv_bfloat16* dst = ((tid < 128) ? Ath : Atl) + st * (32 * 40);
                    *(uint4*)(dst + r * 40 + seg * 8) =
                        *(const uint4*)(src + (size_t)r * KP_H + kc + seg * 8);
                }
#pragma unroll
                for (int q = 0; q < 2; q++) {
                    int it = tid + q * 256;
                    int r = (it & 255) >> 2, seg = it & 3;
                    int gn = n0 + r; if (gn >= NGH) gn = NGH - 1;
                    const __nv_bfloat16* src = (it < 256) ? d_WhcH : d_WhcL;
                    __nv_bfloat16* dst = ((it < 256) ? Bth : Btl) + st * (64 * 40);
                    *(uint4*)(dst + r * 40 + seg * 8) =
                        *(const uint4*)(src + (size_t)gn * KP_H + kc + seg * 8);
                }
                __syncthreads();
#pragma unroll
                for (int kk = 0; kk < 32; kk += 16) {
                    wmma::fragment<wmma::matrix_a, 16,16,16, __nv_bfloat16, wmma::row_major> ah, al;
                    wmma::fragment<wmma::matrix_b, 16,16,16, __nv_bfloat16, wmma::col_major> bh, bl;
                    wmma::load_matrix_sync(ah, Ath + st * (32*40) + (wm * 16) * 40 + kk, 40);
                    wmma::load_matrix_sync(al, Atl + st * (32*40) + (wm * 16) * 40 + kk, 40);
                    wmma::load_matrix_sync(bh, Bth + st * (64*40) + (wn * 16) * 40 + kk, 40);
                    wmma::load_matrix_sync(bl, Btl + st * (64*40) + (wn * 16) * 40 + kk, 40);
                    wmma::mma_sync(acc, ah, bh, acc);
                    wmma::mma_sync(acc, ah, bl, acc);
                    wmma::mma_sync(acc, al, bh, acc);
                }
            }
            __syncthreads();
            wmma::store_matrix_sync(Cs + (wm * 16) * 72 + wn * 16, acc, 72, wmma::mem_row_major);
            __syncthreads();
            for (int idx = tid; idx < 32 * 64; idx += 256) {
                int r = idx >> 6, cc = idx & 63;
                int gn = n0 + cc;
                if (gn < NGH)
                    d_ghp[r * NGH + gn] = Cs[r * 72 + cc] + d_bcomb[gn];
            }
        }
        gridbar();

        // ---- phase B: attention + softmax over batch ----
        if (bid < SRC) {
            const int s = bid;
            int b = tid >> 3, jt = tid & 7;
            const float* hp = d_ghp + b * NGH + 3 * DCH;
            const float* ap = d_annProj + (size_t)(s * BSZ + b) * DCH;
            float acc = 0.f;
            for (int j = jt; j < DCH; j += 8)
                acc += tanhf(hp[j] + ap[j]) * w_a[j];
            for (int off = 4; off; off >>= 1)
                acc += __shfl_down_sync(0xffffffffu, acc, off, 8);
            if (jt == 0) sc[b] = acc;
            __syncthreads();
            if (tid < 32) {
                float v = sc[tid];
                float m = v;
                for (int off = 16; off; off >>= 1) m = fmaxf(m, __shfl_xor_sync(0xffffffffu, m, off));
                float e = expf(v - m);
                float ssum = e;
                for (int off = 16; off; off >>= 1) ssum += __shfl_xor_sync(0xffffffffu, ssum, off);
                float a = e / ssum;
                d_attnS[s * BSZ + tid] = a;
                attns[(size_t)(step + 1) * SRC * BSZ + s * BSZ + tid] = a;
            }
        }
        gridbar();

        // ---- phase C: context + gi + GRU gates ----
        if (bid < BSZ) {
            const int b = bid;
            if (tid < SRC) sat[tid] = d_attnS[tid * BSZ + b];
            __syncthreads();
            for (int e = tid; e < 2 * ECH; e += 256) {
                float acc = 0.f;
                const float* ap = ann + (size_t)b * (2 * ECH) + e;
#pragma unroll 10
                for (int s = 0; s < SRC; s++)
                    acc += sat[s] * ap[(size_t)s * BSZ * (2 * ECH)];
                d_C2[(size_t)(step * BSZ + b) * KP_WP + EMBED + DCH + e] = __float2half(acc);
            }
            const float* gE = d_giEmb + ((size_t)step * BSZ + b) * 3 * DCH;
            for (int j = tid; j < 3 * DCH; j += 256) {
                float acc = gE[j];
                const float* ip = d_annIh + (size_t)b * 3 * DCH + j;
#pragma unroll 10
                for (int s = 0; s < SRC; s++)
                    acc += sat[s] * ip[(size_t)s * BSZ * 3 * DCH];
                sgi[j] = acc;
            }
            __syncthreads();
            const float* gh = d_ghp + b * NGH;
            for (int j = tid; j < DCH; j += 256) {
                float r = 1.f / (1.f + expf(-(sgi[j] + gh[j])));
                float z = 1.f / (1.f + expf(-(sgi[DCH + j] + gh[DCH + j])));
                float n = tanhf(sgi[2 * DCH + j] + r * gh[2 * DCH + j]);
                float hp = d_hbuf[cur][b * DCH + j];
                float hn = (1.f - z) * n + z * hp;
                d_hbuf[cur ^ 1][b * DCH + j] = hn;
                __nv_bfloat16 hh = __float2bfloat16(hn);
                d_hsH[cur ^ 1][b * KP_H + j] = hh;
                d_hsL[cur ^ 1][b * KP_H + j] = __float2bfloat16(hn - __bfloat162float(hh));
                d_C2[(size_t)(step * BSZ + b) * KP_WP + EMBED + j] = __float2half(hp);
                if (step == NSTEP - 1) hidden[b * DCH + j] = hn;
            }
        }
        gridbar();
    }
}

// ============================ small kernels ============================
// bf16 hi/lo split, 8 elems/thread, 16B stores
__global__ void k_split8(const float* __restrict__ src, int sld, int colOff, int rows, int cols,
                         __nv_bfloat16* __restrict__ hi, __nv_bfloat16* __restrict__ lo, int dld)
{
    int i8 = blockIdx.x * blockDim.x + threadIdx.x;
    int total8 = (rows * dld) >> 3;
    if (i8 >= total8) return;
    int i = i8 << 3;
    int r = i / dld, c = i - r * dld;
    float x[8];
    if (c + 7 < cols) {
        const float* p = src + (size_t)r * sld + colOff + c;
        *(float4*)(x)     = *(const float4*)(p);
        *(float4*)(x + 4) = *(const float4*)(p + 4);
    } else {
#pragma unroll
        for (int q = 0; q < 8; q++)
            x[q] = (c + q < cols) ? src[(size_t)r * sld + colOff + c + q] : 0.f;
    }
    __nv_bfloat16 h[8], l[8];
#pragma unroll
    for (int q = 0; q < 8; q++) {
        h[q] = __float2bfloat16(x[q]);
        l[q] = __float2bfloat16(x[q] - __bfloat162float(h[q]));
    }
    *(uint4*)(hi + i) = *(uint4*)h;
    *(uint4*)(lo + i) = *(uint4*)l;
}

// fp16 hi/lo split, 8 elems/thread (W_p)
__global__ void k_splitH8(const float* __restrict__ src, int sld, int colOff, int rows, int cols,
                          __half* __restrict__ hi, __half* __restrict__ lo, int dld)
{
    int i8 = blockIdx.x * blockDim.x + threadIdx.x;
    int total8 = (rows * dld) >> 3;
    if (i8 >= total8) return;
    int i = i8 << 3;
    int r = i / dld, c = i - r * dld;
    float x[8];
    if (c + 7 < cols) {
        const float* p = src + (size_t)r * sld + colOff + c;
        *(float4*)(x)     = *(const float4*)(p);
        *(float4*)(x + 4) = *(const float4*)(p + 4);
    } else {
#pragma unroll
        for (int q = 0; q < 8; q++)
            x[q] = (c + q < cols) ? src[(size_t)r * sld + colOff + c + q] : 0.f;
    }
    __half h[8], l[8];
#pragma unroll
    for (int q = 0; q < 8; q++) {
        h[q] = __float2half(x[q]);
        l[q] = __float2half(x[q] - __half2float(h[q]));
    }
    *(uint4*)(hi + i) = *(uint4*)h;
    *(uint4*)(lo + i) = *(uint4*)l;
}

__global__ void k_zero(float* __restrict__ preds0, float* __restrict__ attns0, int n)
{
    int i = blockIdx.x * blockDim.x + threadIdx.x;
    if (i < n) preds0[i] = 0.f;
    if (i < SRC * BSZ) attns0[i] = 0.f;
}

__global__ void k_bcomb(const float* __restrict__ b_hh)
{
    int i = blockIdx.x * blockDim.x + threadIdx.x;
    if (i < NGH) d_bcomb[i] = (i < 3 * DCH) ? b_hh[i] : 0.f;
}

__global__ void k_embedS(const int* __restrict__ tok, const float* __restrict__ emb)
{
    int i = blockIdx.x * blockDim.x + threadIdx.x;
    if (i >= MROWS * KP_EMB) return;
    int m = i / KP_EMB, e = i - m * KP_EMB;
    float x = (e < EMBED) ? emb[(size_t)tok[m] * EMBED + e] : 0.f;
    __nv_bfloat16 h = __float2bfloat16(x);
    d_EmbH[i] = h;
    d_EmbL[i] = __float2bfloat16(x - __bfloat162float(h));
    if (e < EMBED)
        d_C2[(size_t)m * KP_WP + e] = __float2half(x);
}

__global__ __launch_bounds__(256) void k_lsm(const float* __restrict__ bias, float* __restrict__ preds)
{
    int m = blockIdx.x;
    const float* row = d_logits + (size_t)m * LCOLS;
    float* outr = preds + (size_t)(m + BSZ) * VOCAB;
    int t = threadIdx.x;
    __shared__ float rm[256], rs[256];
    float mx = -1e30f, sum = 0.f;
    for (int v = t; v < VOCAB; v += 256) {
        float x = row[v] + bias[v];
        if (x > mx) { sum = sum * expf(mx - x) + 1.f; mx = x; }
        else sum += expf(x - mx);
    }
    rm[t] = mx; rs[t] = sum; __syncthreads();
    for (int s2 = 128; s2; s2 >>= 1) {
        if (t < s2) {
            float m1 = rm[t], m2 = rm[t + s2];
            float M = fmaxf(m1, m2);
            rs[t] = rs[t] * expf(m1 - M) + rs[t + s2] * expf(m2 - M);
            rm[t] = M;
        }
        __syncthreads();
    }
    float lse = rm[0] + logf(rs[0]);
    for (int v = t; v < VOCAB; v += 256)
        outr[v] = row[v] + bias[v] - lse;
}

// ============================ host ============================
#define SYM(p, s) do { void* _t; cudaGetSymbolAddress(&_t, s); p = (decltype(p))_t; } while (0)

#define SMEM_G128 (128 * 136 * 4)
#define SMEM_G32  (2 * (32 + 128) * 40 * 2 + 1024)

static inline void g128(const __nv_bfloat16* Ah, const __nv_bfloat16* Al, int lda,
                        const __nv_bfloat16* Bh, const __nv_bfloat16* Bl, int ldb,
                        const float* bias, const float* Dadd, int ldd,
                        float* C, int ldc, int M, int N, int KP, int act)
{
    dim3 g((M + 127) / 128, (N + 127) / 128);
    k_wgemm<128><<<g, 256, SMEM_G128>>>(Ah, Al, lda, Bh, Bl, ldb, bias, Dadd, ldd, C, ldc, M, N, KP, act);
}
static inline void g32(const __nv_bfloat16* Ah, const __nv_bfloat16* Al, int lda,
                       const __nv_bfloat16* Bh, const __nv_bfloat16* Bl, int ldb,
                       const float* bias, const float* Dadd, int ldd,
                       float* C, int ldc, int M, int N, int KP, int act)
{
    dim3 g((M + 31) / 32, (N + 127) / 128);
    k_wgemm<32><<<g, 256, SMEM_G32>>>(Ah, Al, lda, Bh, Bl, ldb, bias, Dadd, ldd, C, ldc, M, N, KP, act);
}

extern "C" void kernel_launch(void* const* d_in, const int* in_sizes, int n_in,
                              void* d_out, int out_size)
{
    (void)in_sizes; (void)n_in; (void)out_size;
    const int*   tok  = (const int*)  d_in[0];
    const float* ann  = (const float*)d_in[1];
    const float* emb  = (const float*)d_in[2];
    const float* W_h  = (const float*)d_in[3];
    const float* b_h  = (const float*)d_in[4];
    const float* W_c  = (const float*)d_in[5];
    const float* b_c  = (const float*)d_in[6];
    const float* w_a  = (const float*)d_in[7];
    const float* W_ih = (const float*)d_in[8];
    const float* W_hh = (const float*)d_in[9];
    const float* b_ih = (const float*)d_in[10];
    const float* b_hh = (const float*)d_in[11];
    const float* W_p  = (const float*)d_in[12];
    const float* b_p  = (const float*)d_in[13];

    float* out    = (float*)d_out;
    float* preds  = out;
    float* hidden = out + (size_t)TRGN * BSZ * VOCAB;
    float* attns  = hidden + BSZ * DCH;

    static bool attrDone = false;
    if (!attrDone) {
        cudaFuncSetAttribute(k_wgemm<128>, cudaFuncAttributeMaxDynamicSharedMemorySize, SMEM_G128);
        cudaFuncSetAttribute(k_wgemm<32>,  cudaFuncAttributeMaxDynamicSharedMemorySize, SMEM_G32);
        cudaFuncSetAttribute(k_wgemmBig,   cudaFuncAttributeMaxDynamicSharedMemorySize, SMEM_BIG);
        attrDone = true;
    }

    __half *WpH,*WpL;
    __nv_bfloat16 *annSH,*annSL,*WhcH,*WhcL,*Wc2H,*Wc2L;
    __nv_bfloat16 *Wih1H,*Wih1L,*Wih2H,*Wih2L,*WhH,*WhL,*EmbH,*EmbL,*a0H,*a0L,*hsH,*hsL;
    float *annProj,*annIh,*hbase,*giEmb;
    SYM(WpH, d_Wp16H); SYM(WpL, d_Wp16L);
    SYM(annSH, d_annSH); SYM(annSL, d_annSL);
    SYM(WhcH, d_WhcH); SYM(WhcL, d_WhcL);
    SYM(Wc2H, d_Wc2H); SYM(Wc2L, d_Wc2L);
    SYM(Wih1H, d_Wih1H); SYM(Wih1L, d_Wih1L);
    SYM(Wih2H, d_Wih2H); SYM(Wih2L, d_Wih2L);
    SYM(WhH, d_WhH);   SYM(WhL, d_WhL);
    SYM(EmbH, d_EmbH); SYM(EmbL, d_EmbL);
    SYM(a0H, d_a0H);   SYM(a0L, d_a0L);
    SYM(hsH, d_hsH);   SYM(hsL, d_hsL);
    SYM(annProj, d_annProj); SYM(annIh, d_annIh);
    SYM(hbase, d_hbuf); SYM(giEmb, d_giEmb);

    const int C2W = EMBED + DCH + 2 * ECH;   // 3620
    const int WIHW = EMBED + 2 * ECH;        // 2620

    auto split = [](const float* s, int sld, int off, int rows, int cols,
                    __nv_bfloat16* hi, __nv_bfloat16* lo, int dld) {
        long long tot8 = ((long long)rows * dld) >> 3;
        k_split8<<<(unsigned)((tot8 + 255) / 256), 256>>>(s, sld, off, rows, cols, hi, lo, dld);
    };
    // fp16 split of W_p
    {
        long long tot8 = ((long long)VOCAB * KP_WP) >> 3;
        k_splitH8<<<(unsigned)((tot8 + 255) / 256), 256>>>(W_p, C2W, 0, VOCAB, C2W, WpH, WpL, KP_WP);
    }
    split(W_hh, DCH, 0, 3 * DCH, DCH, WhcH, WhcL, KP_H);
    split(W_c, DCH + 2 * ECH, 0, DCH, DCH, WhcH + (size_t)3*DCH*KP_H,
          WhcL + (size_t)3*DCH*KP_H, KP_H);
    split(W_c, DCH + 2 * ECH, DCH, DCH, 2 * ECH, Wc2H, Wc2L, KP_CTX);
    split(W_ih, WIHW, 0,     3 * DCH, EMBED,   Wih1H, Wih1L, KP_EMB);
    split(W_ih, WIHW, EMBED, 3 * DCH, 2 * ECH, Wih2H, Wih2L, KP_CTX);
    split(W_h, ECH, 0, DCH, ECH, WhH, WhL, KP_H);
    split(ann, 2 * ECH, 0,   SRC * BSZ, 2 * ECH, annSH, annSL, KP_CTX);
    split(ann, 2 * ECH, ECH, BSZ, ECH, a0H, a0L, KP_H);
    k_bcomb<<<(NGH + 255) / 256, 256>>>(b_hh);
    k_zero<<<(BSZ * VOCAB + 255) / 256, 256>>>(preds, attns, BSZ * VOCAB);
    k_embedS<<<(MROWS * KP_EMB + 255) / 256, 256>>>(tok, emb);

    // h0 = tanh(ann0_bw @ W_h^T + b_h)
    g32(a0H, a0L, KP_H, WhH, WhL, KP_H, b_h, nullptr, 0, hbase, DCH, BSZ, DCH, KP_H, 1);
    split(hbase, DCH, 0, BSZ, DCH, hsH, hsL, KP_H);

    // annProj = ann @ W_c2^T + b_c
    g128(annSH, annSL, KP_CTX, Wc2H, Wc2L, KP_CTX, b_c, nullptr, 0,
         annProj, DCH, SRC * BSZ, DCH, KP_CTX, 0);
    // giEmb = embedded @ W_ih1^T + b_ih
    g128(EmbH, EmbL, KP_EMB, Wih1H, Wih1L, KP_EMB, b_ih, nullptr, 0,
         giEmb, 3 * DCH, MROWS, 3 * DCH, KP_EMB, 0);
    // annIh = ann @ W_ih2^T
    g128(annSH, annSL, KP_CTX, Wih2H, Wih2L, KP_CTX, nullptr, nullptr, 0,
         annIh, 3 * DCH, SRC * BSZ, 3 * DCH, KP_CTX, 0);

    // persistent 49-step recurrence (single launch)
    k_recur<<<RGRID, 256>>>(ann, w_a, attns, hidden);

    // big prediction GEMM (fp16, 2 products) -> padded scratch, then bias+log_softmax -> preds
    {
        dim3 g(LROWS / 128, LCOLS / 256);   // 13 x 118
        k_wgemmBig<<<g, 256, SMEM_BIG>>>();
    }
    k_lsm<<<MROWS, 256>>>(b_p, preds);
}